// round 1
// baseline (speedup 1.0000x reference)
#include <cuda_runtime.h>
#include <cuda_bf16.h>
#include <math.h>

// Problem constants (fixed shapes for this problem)
#define B_   16384
#define F_   1024
#define H_   4096
#define O_   1024
#define E_   16
#define CAP_ 2560   // ceil(1.25 * B * 2 / 16)

// ---------------- scratch (device globals; no allocation allowed) ----------
__device__ float  g_h[(size_t)E_ * CAP_ * H_];   // expert hidden activations (fp32)
__device__ int    g_inv[E_ * CAP_];              // slot -> row
__device__ float  g_wslot[E_ * CAP_];            // slot -> combine weight
__device__ int    g_count[E_];                   // rows kept per expert
__device__ int2   g_route_e[B_];                 // per-row top2 expert ids
__device__ float2 g_route_w[B_];                 // per-row top2 softmax weights

// ---------------- helpers ---------------------------------------------------
__device__ __forceinline__ unsigned f2tf32(float x) {
    unsigned r;
    asm("cvt.rna.tf32.f32 %0, %1;" : "=r"(r) : "f"(x));
    return r;
}
__device__ __forceinline__ float f2tf32f(float x) {
    return __uint_as_float(f2tf32(x));
}

__device__ __forceinline__ void mma_tf32(float c[4], const unsigned a[4], const unsigned b[2]) {
    asm volatile(
        "mma.sync.aligned.m16n8k8.row.col.f32.tf32.tf32.f32 "
        "{%0,%1,%2,%3}, {%4,%5,%6,%7}, {%8,%9}, {%0,%1,%2,%3};"
        : "+f"(c[0]), "+f"(c[1]), "+f"(c[2]), "+f"(c[3])
        : "r"(a[0]), "r"(a[1]), "r"(a[2]), "r"(a[3]),
          "r"(b[0]), "r"(b[1]));
}

// ---------------- gating: scores = f @ Wg^T + bg + ebias; top2 + softmax ----
__global__ __launch_bounds__(256) void gating_kernel(
    const float* __restrict__ features,
    const float* __restrict__ Wg,
    const float* __restrict__ bg,
    const float* __restrict__ ebias)
{
    int warp = threadIdx.x >> 5;
    int lane = threadIdx.x & 31;
    int b = blockIdx.x * 8 + warp;
    if (b >= B_) return;

    const float4* f4 = reinterpret_cast<const float4*>(features + (size_t)b * F_);
    float acc[E_];
#pragma unroll
    for (int e = 0; e < E_; e++) acc[e] = 0.f;

    for (int k4 = lane; k4 < F_ / 4; k4 += 32) {
        float4 fv = f4[k4];
#pragma unroll
        for (int e = 0; e < E_; e++) {
            float4 wv = reinterpret_cast<const float4*>(Wg + (size_t)e * F_)[k4];
            acc[e] += fv.x * wv.x + fv.y * wv.y + fv.z * wv.z + fv.w * wv.w;
        }
    }
#pragma unroll
    for (int e = 0; e < E_; e++) {
#pragma unroll
        for (int off = 16; off > 0; off >>= 1)
            acc[e] += __shfl_xor_sync(0xFFFFFFFFu, acc[e], off);
    }
    if (lane == 0) {
        float s[E_];
#pragma unroll
        for (int e = 0; e < E_; e++) s[e] = acc[e] + bg[e] + ebias[e];
        // top-1 (earliest index on tie — strict >)
        int e0 = 0; float s0 = s[0];
#pragma unroll
        for (int e = 1; e < E_; e++) if (s[e] > s0) { s0 = s[e]; e0 = e; }
        // top-2
        int e1 = -1; float s1 = -3.402823e38f;
#pragma unroll
        for (int e = 0; e < E_; e++) if (e != e0 && s[e] > s1) { s1 = s[e]; e1 = e; }
        // softmax over {s0, s1} with TEMP=1.0 (s0 >= s1)
        float z = expf(s1 - s0);
        float w0 = 1.f / (1.f + z);
        float w1 = z / (1.f + z);
        g_route_e[b] = make_int2(e0, e1);
        g_route_w[b] = make_float2(w0, w1);
    }
}

// ---------------- deterministic capacity scan -------------------------------
// One block, 16 warps; warp e scans all rows in order for expert e.
__global__ __launch_bounds__(512) void scan_kernel()
{
    int e = threadIdx.x >> 5;
    int lane = threadIdx.x & 31;
    int base = 0;
    for (int start = 0; start < B_; start += 32) {
        int b = start + lane;
        int2 re = g_route_e[b];
        bool asg = (re.x == e) || (re.y == e);
        unsigned mask = __ballot_sync(0xFFFFFFFFu, asg);
        int pos = base + __popc(mask & ((1u << lane) - 1u));
        if (asg && pos < CAP_) {
            float2 rw = g_route_w[b];
            g_inv[e * CAP_ + pos] = b;
            g_wslot[e * CAP_ + pos] = (re.x == e) ? rw.x : rw.y;
        }
        base += __popc(mask);
    }
    if (lane == 0) g_count[e] = base < CAP_ ? base : CAP_;
}

// ---------------- GEMM tiling constants --------------------------------------
#define BM 128
#define BN 128
#define BK 32
#define SA_STRIDE (BK + 4)    // 36 floats = 144B (16B aligned rows)
#define SB_STRIDE (BN + 4)    // 132 floats = 528B (16B aligned rows)

// ---------------- GEMM1: h[e] = relu(gather(features, inv[e]) @ W1[e] + b1[e])
__global__ __launch_bounds__(256) void gemm1_kernel(
    const float* __restrict__ features,
    const float* __restrict__ W1,
    const float* __restrict__ b1)
{
    const int e = blockIdx.z;
    const int cnt = g_count[e];
    const int m0 = blockIdx.x * BM;
    if (m0 >= cnt) return;
    const int n0 = blockIdx.y * BN;

    __shared__ float sA[BM][SA_STRIDE];
    __shared__ float sB[BK][SB_STRIDE];

    const int tid = threadIdx.x;
    const int lane = tid & 31;
    const int warp = tid >> 5;
    const int wm = warp & 3;           // 4 warp-rows of 32
    const int wn = warp >> 2;          // 2 warp-cols of 64
    const int gID = lane >> 2;
    const int tig = lane & 3;

    // A loader mapping: 4 float4 per thread
    const int a_row = tid >> 3;            // 0..31 (+32 steps)
    const int a_col = (tid & 7) * 4;
    const float* aptr[4];
    bool avalid[4];
#pragma unroll
    for (int i = 0; i < 4; i++) {
        int m = m0 + a_row + i * 32;
        avalid[i] = (m < cnt);
        int r = avalid[i] ? g_inv[e * CAP_ + m] : 0;
        aptr[i] = features + (size_t)r * F_;
    }
    // B loader mapping
    const int b_row = tid >> 5;            // 0..7 (+8 steps)
    const int b_col = (tid & 31) * 4;
    const float* Wbase = W1 + (size_t)e * F_ * H_ + n0;

    float acc[2][8][4];
#pragma unroll
    for (int im = 0; im < 2; im++)
#pragma unroll
        for (int in = 0; in < 8; in++)
#pragma unroll
            for (int j = 0; j < 4; j++) acc[im][in][j] = 0.f;

    float4 pa[4], pb[4];
    // prefetch k0 = 0
#pragma unroll
    for (int i = 0; i < 4; i++)
        pa[i] = avalid[i] ? *reinterpret_cast<const float4*>(aptr[i] + a_col)
                          : make_float4(0.f, 0.f, 0.f, 0.f);
#pragma unroll
    for (int i = 0; i < 4; i++)
        pb[i] = *reinterpret_cast<const float4*>(Wbase + (size_t)(b_row + 8 * i) * H_ + b_col);

#pragma unroll
    for (int i = 0; i < 4; i++) {
        float4 t = make_float4(f2tf32f(pa[i].x), f2tf32f(pa[i].y), f2tf32f(pa[i].z), f2tf32f(pa[i].w));
        *reinterpret_cast<float4*>(&sA[a_row + 32 * i][a_col]) = t;
        float4 u = make_float4(f2tf32f(pb[i].x), f2tf32f(pb[i].y), f2tf32f(pb[i].z), f2tf32f(pb[i].w));
        *reinterpret_cast<float4*>(&sB[b_row + 8 * i][b_col]) = u;
    }
    __syncthreads();

    for (int k0 = 0; k0 < F_; k0 += BK) {
        const bool more = (k0 + BK) < F_;
        if (more) {
            int knext = k0 + BK;
#pragma unroll
            for (int i = 0; i < 4; i++)
                pa[i] = avalid[i] ? *reinterpret_cast<const float4*>(aptr[i] + knext + a_col)
                                  : make_float4(0.f, 0.f, 0.f, 0.f);
#pragma unroll
            for (int i = 0; i < 4; i++)
                pb[i] = *reinterpret_cast<const float4*>(Wbase + (size_t)(knext + b_row + 8 * i) * H_ + b_col);
        }
        // compute from smem
#pragma unroll
        for (int kk = 0; kk < 4; kk++) {
            unsigned af[2][4];
#pragma unroll
            for (int im = 0; im < 2; im++) {
                int r = wm * 32 + im * 16 + gID;
                af[im][0] = __float_as_uint(sA[r    ][kk * 8 + tig    ]);
                af[im][1] = __float_as_uint(sA[r + 8][kk * 8 + tig    ]);
                af[im][2] = __float_as_uint(sA[r    ][kk * 8 + tig + 4]);
                af[im][3] = __float_as_uint(sA[r + 8][kk * 8 + tig + 4]);
            }
            unsigned bf[8][2];
#pragma unroll
            for (int in = 0; in < 8; in++) {
                int c = wn * 64 + in * 8 + gID;
                bf[in][0] = __float_as_uint(sB[kk * 8 + tig    ][c]);
                bf[in][1] = __float_as_uint(sB[kk * 8 + tig + 4][c]);
            }
#pragma unroll
            for (int im = 0; im < 2; im++)
#pragma unroll
                for (int in = 0; in < 8; in++)
                    mma_tf32(acc[im][in], af[im], bf[in]);
        }
        __syncthreads();
        if (more) {
#pragma unroll
            for (int i = 0; i < 4; i++) {
                float4 t = make_float4(f2tf32f(pa[i].x), f2tf32f(pa[i].y), f2tf32f(pa[i].z), f2tf32f(pa[i].w));
                *reinterpret_cast<float4*>(&sA[a_row + 32 * i][a_col]) = t;
                float4 u = make_float4(f2tf32f(pb[i].x), f2tf32f(pb[i].y), f2tf32f(pb[i].z), f2tf32f(pb[i].w));
                *reinterpret_cast<float4*>(&sB[b_row + 8 * i][b_col]) = u;
            }
            __syncthreads();
        }
    }

    // epilogue: relu(acc + b1) -> g_h
    float* hbase = g_h + (size_t)e * CAP_ * H_;
    const float* b1e = b1 + (size_t)e * H_;
#pragma unroll
    for (int im = 0; im < 2; im++) {
#pragma unroll
        for (int in = 0; in < 8; in++) {
            int n = n0 + wn * 64 + in * 8 + tig * 2;
            float bx = b1e[n], by = b1e[n + 1];
            int mlo = m0 + wm * 32 + im * 16 + gID;
            float2 v0 = make_float2(fmaxf(acc[im][in][0] + bx, 0.f),
                                    fmaxf(acc[im][in][1] + by, 0.f));
            float2 v1 = make_float2(fmaxf(acc[im][in][2] + bx, 0.f),
                                    fmaxf(acc[im][in][3] + by, 0.f));
            *reinterpret_cast<float2*>(&hbase[(size_t)mlo * H_ + n]) = v0;
            *reinterpret_cast<float2*>(&hbase[(size_t)(mlo + 8) * H_ + n]) = v1;
        }
    }
}

// ---------------- GEMM2: out[inv] += w * (h[e] @ W2[e] + b2[e]) --------------
__global__ __launch_bounds__(256) void gemm2_kernel(
    const float* __restrict__ W2,
    const float* __restrict__ b2,
    float* __restrict__ out)
{
    const int e = blockIdx.z;
    const int cnt = g_count[e];
    const int m0 = blockIdx.x * BM;
    if (m0 >= cnt) return;
    const int n0 = blockIdx.y * BN;

    __shared__ float sA[BM][SA_STRIDE];
    __shared__ float sB[BK][SB_STRIDE];

    const int tid = threadIdx.x;
    const int lane = tid & 31;
    const int warp = tid >> 5;
    const int wm = warp & 3;
    const int wn = warp >> 2;
    const int gID = lane >> 2;
    const int tig = lane & 3;

    const int a_row = tid >> 3;
    const int a_col = (tid & 7) * 4;
    const float* Abase = g_h + (size_t)e * CAP_ * H_;

    const int b_row = tid >> 5;
    const int b_col = (tid & 31) * 4;
    const float* Wbase = W2 + (size_t)e * H_ * O_ + n0;

    float acc[2][8][4];
#pragma unroll
    for (int im = 0; im < 2; im++)
#pragma unroll
        for (int in = 0; in < 8; in++)
#pragma unroll
            for (int j = 0; j < 4; j++) acc[im][in][j] = 0.f;

    float4 pa[4], pb[4];
#pragma unroll
    for (int i = 0; i < 4; i++)
        pa[i] = *reinterpret_cast<const float4*>(Abase + (size_t)(m0 + a_row + 32 * i) * H_ + a_col);
#pragma unroll
    for (int i = 0; i < 4; i++)
        pb[i] = *reinterpret_cast<const float4*>(Wbase + (size_t)(b_row + 8 * i) * O_ + b_col);

#pragma unroll
    for (int i = 0; i < 4; i++) {
        float4 t = make_float4(f2tf32f(pa[i].x), f2tf32f(pa[i].y), f2tf32f(pa[i].z), f2tf32f(pa[i].w));
        *reinterpret_cast<float4*>(&sA[a_row + 32 * i][a_col]) = t;
        float4 u = make_float4(f2tf32f(pb[i].x), f2tf32f(pb[i].y), f2tf32f(pb[i].z), f2tf32f(pb[i].w));
        *reinterpret_cast<float4*>(&sB[b_row + 8 * i][b_col]) = u;
    }
    __syncthreads();

    for (int k0 = 0; k0 < H_; k0 += BK) {
        const bool more = (k0 + BK) < H_;
        if (more) {
            int knext = k0 + BK;
#pragma unroll
            for (int i = 0; i < 4; i++)
                pa[i] = *reinterpret_cast<const float4*>(Abase + (size_t)(m0 + a_row + 32 * i) * H_ + knext + a_col);
#pragma unroll
            for (int i = 0; i < 4; i++)
                pb[i] = *reinterpret_cast<const float4*>(Wbase + (size_t)(knext + b_row + 8 * i) * O_ + b_col);
        }
#pragma unroll
        for (int kk = 0; kk < 4; kk++) {
            unsigned af[2][4];
#pragma unroll
            for (int im = 0; im < 2; im++) {
                int r = wm * 32 + im * 16 + gID;
                af[im][0] = __float_as_uint(sA[r    ][kk * 8 + tig    ]);
                af[im][1] = __float_as_uint(sA[r + 8][kk * 8 + tig    ]);
                af[im][2] = __float_as_uint(sA[r    ][kk * 8 + tig + 4]);
                af[im][3] = __float_as_uint(sA[r + 8][kk * 8 + tig + 4]);
            }
            unsigned bf[8][2];
#pragma unroll
            for (int in = 0; in < 8; in++) {
                int c = wn * 64 + in * 8 + gID;
                bf[in][0] = __float_as_uint(sB[kk * 8 + tig    ][c]);
                bf[in][1] = __float_as_uint(sB[kk * 8 + tig + 4][c]);
            }
#pragma unroll
            for (int im = 0; im < 2; im++)
#pragma unroll
                for (int in = 0; in < 8; in++)
                    mma_tf32(acc[im][in], af[im], bf[in]);
        }
        __syncthreads();
        if (more) {
#pragma unroll
            for (int i = 0; i < 4; i++) {
                float4 t = make_float4(f2tf32f(pa[i].x), f2tf32f(pa[i].y), f2tf32f(pa[i].z), f2tf32f(pa[i].w));
                *reinterpret_cast<float4*>(&sA[a_row + 32 * i][a_col]) = t;
                float4 u = make_float4(f2tf32f(pb[i].x), f2tf32f(pb[i].y), f2tf32f(pb[i].z), f2tf32f(pb[i].w));
                *reinterpret_cast<float4*>(&sB[b_row + 8 * i][b_col]) = u;
            }
            __syncthreads();
        }
    }

    // epilogue: scatter-add w * (acc + b2) into out rows
    const float* b2e = b2 + (size_t)e * O_;
#pragma unroll
    for (int im = 0; im < 2; im++) {
        int mlo = m0 + wm * 32 + im * 16 + gID;
        int mhi = mlo + 8;
        bool vlo = mlo < cnt;
        bool vhi = mhi < cnt;
        int rlo = vlo ? g_inv[e * CAP_ + mlo] : 0;
        int rhi = vhi ? g_inv[e * CAP_ + mhi] : 0;
        float wlo = vlo ? g_wslot[e * CAP_ + mlo] : 0.f;
        float whi = vhi ? g_wslot[e * CAP_ + mhi] : 0.f;
#pragma unroll
        for (int in = 0; in < 8; in++) {
            int n = n0 + wn * 64 + in * 8 + tig * 2;
            float bx = b2e[n], by = b2e[n + 1];
            if (vlo) {
                atomicAdd(&out[(size_t)rlo * O_ + n],     wlo * (acc[im][in][0] + bx));
                atomicAdd(&out[(size_t)rlo * O_ + n + 1], wlo * (acc[im][in][1] + by));
            }
            if (vhi) {
                atomicAdd(&out[(size_t)rhi * O_ + n],     whi * (acc[im][in][2] + bx));
                atomicAdd(&out[(size_t)rhi * O_ + n + 1], whi * (acc[im][in][3] + by));
            }
        }
    }
}

// ---------------- launch ------------------------------------------------------
extern "C" void kernel_launch(void* const* d_in, const int* in_sizes, int n_in,
                              void* d_out, int out_size)
{
    const float* features = (const float*)d_in[0];
    const float* Wg       = (const float*)d_in[1];
    const float* bg       = (const float*)d_in[2];
    const float* W1       = (const float*)d_in[3];
    const float* b1       = (const float*)d_in[4];
    const float* W2       = (const float*)d_in[5];
    const float* b2       = (const float*)d_in[6];
    const float* ebias    = (const float*)d_in[7];
    float* out = (float*)d_out;

    cudaMemsetAsync(out, 0, (size_t)B_ * O_ * sizeof(float), 0);
    gating_kernel<<<B_ / 8, 256>>>(features, Wg, bg, ebias);
    scan_kernel<<<1, 512>>>();
    gemm1_kernel<<<dim3(CAP_ / BM, H_ / BN, E_), 256>>>(features, W1, b1);
    gemm2_kernel<<<dim3(CAP_ / BM, O_ / BN, E_), 256>>>(W2, b2, out);
}

// round 3
// speedup vs baseline: 1.6485x; 1.6485x over previous
#include <cuda_runtime.h>
#include <cuda_fp16.h>
#include <math.h>
#include <stdint.h>

// Problem constants
#define B_   16384
#define F_   1024
#define H_   4096
#define O_   1024
#define E_   16
#define CAP_ 2560   // ceil(1.25 * B * 2 / 16)

// ---------------- scratch (device globals; no allocation allowed) ----------
__device__ __half  g_h[(size_t)E_ * CAP_ * H_];     // expert hidden activations (fp16)
__device__ __half  g_featr[(size_t)B_ * F_];        // features in fp16
__device__ __half  g_W1h[(size_t)E_ * F_ * H_];     // W1 in fp16
__device__ __half  g_W2h[(size_t)E_ * H_ * O_];     // W2 in fp16
__device__ int     g_inv[E_ * CAP_];
__device__ float   g_wslot[E_ * CAP_];
__device__ int     g_count[E_];
__device__ int2    g_route_e[B_];
__device__ float2  g_route_w[B_];

// ---------------- helpers ---------------------------------------------------
__device__ __forceinline__ uint32_t smem_u32(const void* p) {
    uint32_t a;
    asm("{ .reg .u64 t; cvta.to.shared.u64 t, %1; cvt.u32.u64 %0, t; }" : "=r"(a) : "l"(p));
    return a;
}
__device__ __forceinline__ void cp_async16(uint32_t dst, const void* src) {
    asm volatile("cp.async.cg.shared.global [%0], [%1], 16;" :: "r"(dst), "l"(src));
}
__device__ __forceinline__ void cp_commit() { asm volatile("cp.async.commit_group;" ::: "memory"); }
template<int N> __device__ __forceinline__ void cp_wait() {
    asm volatile("cp.async.wait_group %0;" :: "n"(N) : "memory");
}
__device__ __forceinline__ void ldsm_x4(uint32_t r[4], uint32_t addr) {
    asm volatile("ldmatrix.sync.aligned.m8n8.x4.shared.b16 {%0,%1,%2,%3}, [%4];"
                 : "=r"(r[0]), "=r"(r[1]), "=r"(r[2]), "=r"(r[3]) : "r"(addr));
}
__device__ __forceinline__ void ldsm_x4_t(uint32_t r[4], uint32_t addr) {
    asm volatile("ldmatrix.sync.aligned.m8n8.x4.trans.shared.b16 {%0,%1,%2,%3}, [%4];"
                 : "=r"(r[0]), "=r"(r[1]), "=r"(r[2]), "=r"(r[3]) : "r"(addr));
}
__device__ __forceinline__ void mma_f16(float c[4], const uint32_t a[4],
                                        uint32_t b0, uint32_t b1) {
    asm volatile(
        "mma.sync.aligned.m16n8k16.row.col.f32.f16.f16.f32 "
        "{%0,%1,%2,%3}, {%4,%5,%6,%7}, {%8,%9}, {%0,%1,%2,%3};"
        : "+f"(c[0]), "+f"(c[1]), "+f"(c[2]), "+f"(c[3])
        : "r"(a[0]), "r"(a[1]), "r"(a[2]), "r"(a[3]), "r"(b0), "r"(b1));
}

// ---------------- fp32 -> fp16 conversion ------------------------------------
__global__ __launch_bounds__(256) void f2h_kernel(const float* __restrict__ src,
                                                  __half* __restrict__ dst)
{
    size_t i = (size_t)blockIdx.x * 256 + threadIdx.x;   // float4 index
    float4 v = reinterpret_cast<const float4*>(src)[i];
    __half2 h0 = __floats2half2_rn(v.x, v.y);
    __half2 h1 = __floats2half2_rn(v.z, v.w);
    reinterpret_cast<__half2*>(dst)[2 * i]     = h0;
    reinterpret_cast<__half2*>(dst)[2 * i + 1] = h1;
}

// ---------------- gating ----------------------------------------------------
__global__ __launch_bounds__(256) void gating_kernel(
    const float* __restrict__ features,
    const float* __restrict__ Wg,
    const float* __restrict__ bg,
    const float* __restrict__ ebias)
{
    int warp = threadIdx.x >> 5;
    int lane = threadIdx.x & 31;
    int b = blockIdx.x * 8 + warp;
    if (b >= B_) return;

    const float4* f4 = reinterpret_cast<const float4*>(features + (size_t)b * F_);
    float acc[E_];
#pragma unroll
    for (int e = 0; e < E_; e++) acc[e] = 0.f;

    for (int k4 = lane; k4 < F_ / 4; k4 += 32) {
        float4 fv = f4[k4];
#pragma unroll
        for (int e = 0; e < E_; e++) {
            float4 wv = reinterpret_cast<const float4*>(Wg + (size_t)e * F_)[k4];
            acc[e] += fv.x * wv.x + fv.y * wv.y + fv.z * wv.z + fv.w * wv.w;
        }
    }
#pragma unroll
    for (int e = 0; e < E_; e++) {
#pragma unroll
        for (int off = 16; off > 0; off >>= 1)
            acc[e] += __shfl_xor_sync(0xFFFFFFFFu, acc[e], off);
    }
    if (lane == 0) {
        float s[E_];
#pragma unroll
        for (int e = 0; e < E_; e++) s[e] = acc[e] + bg[e] + ebias[e];
        int e0 = 0; float s0 = s[0];
#pragma unroll
        for (int e = 1; e < E_; e++) if (s[e] > s0) { s0 = s[e]; e0 = e; }
        int e1 = -1; float s1 = -3.402823e38f;
#pragma unroll
        for (int e = 0; e < E_; e++) if (e != e0 && s[e] > s1) { s1 = s[e]; e1 = e; }
        float z = expf(s1 - s0);
        float w0 = 1.f / (1.f + z);
        float w1 = z / (1.f + z);
        g_route_e[b] = make_int2(e0, e1);
        g_route_w[b] = make_float2(w0, w1);
    }
}

// ---------------- deterministic capacity scan -------------------------------
__global__ __launch_bounds__(512) void scan_kernel()
{
    int e = threadIdx.x >> 5;
    int lane = threadIdx.x & 31;
    int base = 0;
    for (int start = 0; start < B_; start += 32) {
        int b = start + lane;
        int2 re = g_route_e[b];
        bool asg = (re.x == e) || (re.y == e);
        unsigned mask = __ballot_sync(0xFFFFFFFFu, asg);
        int pos = base + __popc(mask & ((1u << lane) - 1u));
        if (asg && pos < CAP_) {
            float2 rw = g_route_w[b];
            g_inv[e * CAP_ + pos] = b;
            g_wslot[e * CAP_ + pos] = (re.x == e) ? rw.x : rw.y;
        }
        base += __popc(mask);
    }
    if (lane == 0) g_count[e] = base < CAP_ ? base : CAP_;
}

// ---------------- fp16 tensor-core grouped GEMM ------------------------------
// CTA tile 128(m) x 128(n), BK=32, 4-stage cp.async pipeline.
// 8 warps: wm = wid&3 (m32 tiles), wn = wid>>2 (n64 tiles).
// smem per stage: sA 128 rows x 80B (64B data) = 10240B; sB 32 rows x 272B (256B data) = 8704B.
#define APITCH 80
#define BPITCH 272
#define STAGE_BYTES (128 * APITCH + 32 * BPITCH)   // 18944
#define NSTAGE 4
#define SMEM_TOTAL (NSTAGE * STAGE_BYTES)

template<int KD, int ND, bool G1>
__global__ __launch_bounds__(256, 1) void moe_gemm(
    const float* __restrict__ bias, float* __restrict__ out)
{
    const int e = blockIdx.z;
    const int cnt = g_count[e];
    const int m0 = blockIdx.x * 128;
    if (m0 >= cnt) return;
    const int n0 = blockIdx.y * 128;
    constexpr int NK = KD / 32;

    extern __shared__ char smem_raw[];
    const uint32_t sbase = smem_u32(smem_raw);

    const int tid  = threadIdx.x;
    const int lane = tid & 31;
    const int wid  = tid >> 5;
    const int wm   = wid & 3;
    const int wn   = wid >> 2;

    // ---- loader setup: 4 cp.async (16B) per thread per stage ----
    // A tasks: t = tid + 256*i -> arow = t>>2 (0..127), achunk = t&3
    // B tasks: t = tid + 256*i -> brow = t>>4 (0..31),  bchunk = t&15
    const __half* pA[2];
    uint32_t dA[2], dB[2];
    const __half* pB[2];
#pragma unroll
    for (int i = 0; i < 2; i++) {
        int t = tid + 256 * i;
        int arow = t >> 2, achunk = t & 3;
        if (G1) {
            int m = m0 + arow;
            int r = (m < cnt) ? g_inv[e * CAP_ + m] : 0;
            pA[i] = g_featr + (size_t)r * KD + achunk * 8;
        } else {
            pA[i] = g_h + ((size_t)e * CAP_ + m0 + arow) * KD + achunk * 8;
        }
        dA[i] = arow * APITCH + achunk * 16;

        int brow = t >> 4, bchunk = t & 15;
        const __half* W = G1 ? g_W1h : g_W2h;
        pB[i] = W + (size_t)e * KD * ND + (size_t)brow * ND + n0 + bchunk * 8;
        dB[i] = 128 * APITCH + brow * BPITCH + bchunk * 16;
    }

    auto load_stage = [&](int ko, int s) {
        uint32_t st = sbase + s * STAGE_BYTES;
#pragma unroll
        for (int i = 0; i < 2; i++)
            cp_async16(st + dA[i], pA[i] + (size_t)ko * 32);
#pragma unroll
        for (int i = 0; i < 2; i++)
            cp_async16(st + dB[i], pB[i] + (size_t)ko * 32 * ND);
        cp_commit();
    };

    load_stage(0, 0); load_stage(1, 1); load_stage(2, 2);

    // ---- ldmatrix address lane components ----
    const int a_lmrow = wm * 32 + (lane & 7) + ((lane >> 3) & 1) * 8;
    const int a_kb    = (lane >> 4);                 // 16B chunk within k16
    const int b_k     = (lane & 7) + ((lane >> 3) & 1) * 8;
    const int b_nb    = (lane >> 4) * 8;             // +8 halves for n-hi tiles

    float acc[2][8][4];
#pragma unroll
    for (int im = 0; im < 2; im++)
#pragma unroll
        for (int jn = 0; jn < 8; jn++)
#pragma unroll
            for (int q = 0; q < 4; q++) acc[im][jn][q] = 0.f;

    for (int i = 0; i < NK; i++) {
        if (i <= NK - 3)      cp_wait<2>();
        else if (i == NK - 2) cp_wait<1>();
        else                  cp_wait<0>();
        __syncthreads();
        if (i + 3 < NK) load_stage(i + 3, (i + 3) & 3);

        const uint32_t st = sbase + (i & 3) * STAGE_BYTES;
#pragma unroll
        for (int kk = 0; kk < 2; kk++) {
            uint32_t a[2][4], b[4][4];
#pragma unroll
            for (int im = 0; im < 2; im++)
                ldsm_x4(a[im], st + (a_lmrow + im * 16) * APITCH + (kk * 2 + a_kb) * 16);
#pragma unroll
            for (int j = 0; j < 4; j++)
                ldsm_x4_t(b[j], st + 128 * APITCH + (kk * 16 + b_k) * BPITCH
                                  + (wn * 64 + j * 16 + b_nb) * 2);
#pragma unroll
            for (int im = 0; im < 2; im++)
#pragma unroll
                for (int jn = 0; jn < 8; jn++)
                    mma_f16(acc[im][jn], a[im], b[jn >> 1][(jn & 1) * 2],
                            b[jn >> 1][(jn & 1) * 2 + 1]);
        }
        __syncthreads();
    }

    // ---- epilogue ----
    const int gID = lane >> 2;
    const int tig = lane & 3;
#pragma unroll
    for (int im = 0; im < 2; im++) {
        int r0 = m0 + wm * 32 + im * 16 + gID;
        int r1 = r0 + 8;
        bool v0 = r0 < cnt, v1 = r1 < cnt;
        if (G1) {
            __half* h0 = g_h + ((size_t)e * CAP_ + r0) * ND;
            __half* h1 = g_h + ((size_t)e * CAP_ + r1) * ND;
#pragma unroll
            for (int jn = 0; jn < 8; jn++) {
                int c = n0 + wn * 64 + jn * 8 + tig * 2;
                float bx = bias[c], by = bias[c + 1];
                if (v0) {
                    __half2 h = __floats2half2_rn(fmaxf(acc[im][jn][0] + bx, 0.f),
                                                  fmaxf(acc[im][jn][1] + by, 0.f));
                    *reinterpret_cast<__half2*>(h0 + c) = h;
                }
                if (v1) {
                    __half2 h = __floats2half2_rn(fmaxf(acc[im][jn][2] + bx, 0.f),
                                                  fmaxf(acc[im][jn][3] + by, 0.f));
                    *reinterpret_cast<__half2*>(h1 + c) = h;
                }
            }
        } else {
            int   i0 = v0 ? g_inv[e * CAP_ + r0] : 0;
            int   i1 = v1 ? g_inv[e * CAP_ + r1] : 0;
            float w0 = v0 ? g_wslot[e * CAP_ + r0] : 0.f;
            float w1 = v1 ? g_wslot[e * CAP_ + r1] : 0.f;
#pragma unroll
            for (int jn = 0; jn < 8; jn++) {
                int c = n0 + wn * 64 + jn * 8 + tig * 2;
                float bx = bias[c], by = bias[c + 1];
                if (v0) {
                    atomicAdd(out + (size_t)i0 * ND + c,     w0 * (acc[im][jn][0] + bx));
                    atomicAdd(out + (size_t)i0 * ND + c + 1, w0 * (acc[im][jn][1] + by));
                }
                if (v1) {
                    atomicAdd(out + (size_t)i1 * ND + c,     w1 * (acc[im][jn][2] + bx));
                    atomicAdd(out + (size_t)i1 * ND + c + 1, w1 * (acc[im][jn][3] + by));
                }
            }
        }
    }
}

// ---------------- launch ------------------------------------------------------
extern "C" void kernel_launch(void* const* d_in, const int* in_sizes, int n_in,
                              void* d_out, int out_size)
{
    const float* features = (const float*)d_in[0];
    const float* Wg       = (const float*)d_in[1];
    const float* bg       = (const float*)d_in[2];
    const float* W1       = (const float*)d_in[3];
    const float* b1       = (const float*)d_in[4];
    const float* W2       = (const float*)d_in[5];
    const float* b2       = (const float*)d_in[6];
    const float* ebias    = (const float*)d_in[7];
    float* out = (float*)d_out;

    cudaFuncSetAttribute(moe_gemm<F_, H_, true>,
                         cudaFuncAttributeMaxDynamicSharedMemorySize, SMEM_TOTAL);
    cudaFuncSetAttribute(moe_gemm<H_, O_, false>,
                         cudaFuncAttributeMaxDynamicSharedMemorySize, SMEM_TOTAL);

    cudaMemsetAsync(out, 0, (size_t)B_ * O_ * sizeof(float), 0);

    __half* d_featr; cudaGetSymbolAddress((void**)&d_featr, g_featr);
    __half* d_W1h;   cudaGetSymbolAddress((void**)&d_W1h, g_W1h);
    __half* d_W2h;   cudaGetSymbolAddress((void**)&d_W2h, g_W2h);

    f2h_kernel<<<(B_ * F_ / 4) / 256, 256>>>(features, d_featr);
    f2h_kernel<<<((size_t)E_ * F_ * H_ / 4) / 256, 256>>>(W1, d_W1h);
    f2h_kernel<<<((size_t)E_ * H_ * O_ / 4) / 256, 256>>>(W2, d_W2h);
    gating_kernel<<<B_ / 8, 256>>>(features, Wg, bg, ebias);
    scan_kernel<<<1, 512>>>();

    moe_gemm<F_, H_, true ><<<dim3(CAP_ / 128, H_ / 128, E_), 256, SMEM_TOTAL>>>(b1, nullptr);
    moe_gemm<H_, O_, false><<<dim3(CAP_ / 128, O_ / 128, E_), 256, SMEM_TOTAL>>>(b2, out);
}

// round 4
// speedup vs baseline: 1.7379x; 1.0543x over previous
#include <cuda_runtime.h>
#include <cuda_fp16.h>
#include <math.h>
#include <stdint.h>

// Problem constants
#define B_   16384
#define F_   1024
#define H_   4096
#define O_   1024
#define E_   16
#define CAP_ 2560   // ceil(1.25 * B * 2 / 16)

// ---------------- scratch (device globals; no allocation allowed) ----------
__device__ __half  g_h[(size_t)E_ * CAP_ * H_];     // expert hidden activations (fp16)
__device__ __half  g_featr[(size_t)B_ * F_];        // features in fp16
__device__ __half  g_W1h[(size_t)E_ * F_ * H_];     // W1 in fp16
__device__ __half  g_W2h[(size_t)E_ * H_ * O_];     // W2 in fp16
__device__ int     g_inv[E_ * CAP_];
__device__ float   g_wslot[E_ * CAP_];
__device__ int     g_count[E_];
__device__ int2    g_route_e[B_];
__device__ float2  g_route_w[B_];

// ---------------- helpers ---------------------------------------------------
__device__ __forceinline__ uint32_t smem_u32(const void* p) {
    uint32_t a;
    asm("{ .reg .u64 t; cvta.to.shared.u64 t, %1; cvt.u32.u64 %0, t; }" : "=r"(a) : "l"(p));
    return a;
}
__device__ __forceinline__ void cp_async16(uint32_t dst, const void* src) {
    asm volatile("cp.async.cg.shared.global [%0], [%1], 16;" :: "r"(dst), "l"(src));
}
__device__ __forceinline__ void cp_commit() { asm volatile("cp.async.commit_group;" ::: "memory"); }
template<int N> __device__ __forceinline__ void cp_wait() {
    asm volatile("cp.async.wait_group %0;" :: "n"(N) : "memory");
}
__device__ __forceinline__ void ldsm_x4(uint32_t r[4], uint32_t addr) {
    asm volatile("ldmatrix.sync.aligned.m8n8.x4.shared.b16 {%0,%1,%2,%3}, [%4];"
                 : "=r"(r[0]), "=r"(r[1]), "=r"(r[2]), "=r"(r[3]) : "r"(addr));
}
__device__ __forceinline__ void ldsm_x4_t(uint32_t r[4], uint32_t addr) {
    asm volatile("ldmatrix.sync.aligned.m8n8.x4.trans.shared.b16 {%0,%1,%2,%3}, [%4];"
                 : "=r"(r[0]), "=r"(r[1]), "=r"(r[2]), "=r"(r[3]) : "r"(addr));
}
__device__ __forceinline__ void mma_f16(float c[4], const uint32_t a[4],
                                        uint32_t b0, uint32_t b1) {
    asm volatile(
        "mma.sync.aligned.m16n8k16.row.col.f32.f16.f16.f32 "
        "{%0,%1,%2,%3}, {%4,%5,%6,%7}, {%8,%9}, {%0,%1,%2,%3};"
        : "+f"(c[0]), "+f"(c[1]), "+f"(c[2]), "+f"(c[3])
        : "r"(a[0]), "r"(a[1]), "r"(a[2]), "r"(a[3]), "r"(b0), "r"(b1));
}

// ---------------- fp32 -> fp16 conversion ------------------------------------
__global__ __launch_bounds__(256) void f2h_kernel(const float* __restrict__ src,
                                                  __half* __restrict__ dst)
{
    size_t i = (size_t)blockIdx.x * 256 + threadIdx.x;   // float4 index
    float4 v = reinterpret_cast<const float4*>(src)[i];
    __half2 h0 = __floats2half2_rn(v.x, v.y);
    __half2 h1 = __floats2half2_rn(v.z, v.w);
    reinterpret_cast<__half2*>(dst)[2 * i]     = h0;
    reinterpret_cast<__half2*>(dst)[2 * i + 1] = h1;
}

// ---------------- gating ----------------------------------------------------
__global__ __launch_bounds__(256) void gating_kernel(
    const float* __restrict__ features,
    const float* __restrict__ Wg,
    const float* __restrict__ bg,
    const float* __restrict__ ebias)
{
    int warp = threadIdx.x >> 5;
    int lane = threadIdx.x & 31;
    int b = blockIdx.x * 8 + warp;
    if (b >= B_) return;

    const float4* f4 = reinterpret_cast<const float4*>(features + (size_t)b * F_);
    float acc[E_];
#pragma unroll
    for (int e = 0; e < E_; e++) acc[e] = 0.f;

    for (int k4 = lane; k4 < F_ / 4; k4 += 32) {
        float4 fv = f4[k4];
#pragma unroll
        for (int e = 0; e < E_; e++) {
            float4 wv = reinterpret_cast<const float4*>(Wg + (size_t)e * F_)[k4];
            acc[e] += fv.x * wv.x + fv.y * wv.y + fv.z * wv.z + fv.w * wv.w;
        }
    }
#pragma unroll
    for (int e = 0; e < E_; e++) {
#pragma unroll
        for (int off = 16; off > 0; off >>= 1)
            acc[e] += __shfl_xor_sync(0xFFFFFFFFu, acc[e], off);
    }
    if (lane == 0) {
        float s[E_];
#pragma unroll
        for (int e = 0; e < E_; e++) s[e] = acc[e] + bg[e] + ebias[e];
        int e0 = 0; float s0 = s[0];
#pragma unroll
        for (int e = 1; e < E_; e++) if (s[e] > s0) { s0 = s[e]; e0 = e; }
        int e1 = -1; float s1 = -3.402823e38f;
#pragma unroll
        for (int e = 0; e < E_; e++) if (e != e0 && s[e] > s1) { s1 = s[e]; e1 = e; }
        float z = expf(s1 - s0);
        float w0 = 1.f / (1.f + z);
        float w1 = z / (1.f + z);
        g_route_e[b] = make_int2(e0, e1);
        g_route_w[b] = make_float2(w0, w1);
    }
}

// ---------------- deterministic capacity scan -------------------------------
__global__ __launch_bounds__(512) void scan_kernel()
{
    int e = threadIdx.x >> 5;
    int lane = threadIdx.x & 31;
    int base = 0;
    for (int start = 0; start < B_; start += 32) {
        int b = start + lane;
        int2 re = g_route_e[b];
        bool asg = (re.x == e) || (re.y == e);
        unsigned mask = __ballot_sync(0xFFFFFFFFu, asg);
        int pos = base + __popc(mask & ((1u << lane) - 1u));
        if (asg && pos < CAP_) {
            float2 rw = g_route_w[b];
            g_inv[e * CAP_ + pos] = b;
            g_wslot[e * CAP_ + pos] = (re.x == e) ? rw.x : rw.y;
        }
        base += __popc(mask);
    }
    if (lane == 0) g_count[e] = base < CAP_ ? base : CAP_;
}

// ---------------- fp16 tensor-core grouped GEMM ------------------------------
// CTA tile 256(m) x 128(n), BK=32, 4-stage cp.async pipeline, 512 threads.
// 16 warps: wm = wid&7 (8 m-warps of 32 rows), wn = wid>>3 (2 n-warps of 64).
// smem per stage: sA 256 x 80B = 20480B; sB 32 x 272B = 8704B -> 29184B.
#define APITCH 80
#define BPITCH 272
#define STAGE_BYTES (256 * APITCH + 32 * BPITCH)   // 29184
#define NSTAGE 4
#define SMEM_TOTAL (NSTAGE * STAGE_BYTES)          // 116736

template<int KD, int ND, bool G1>
__global__ __launch_bounds__(512, 1) void moe_gemm(
    const float* __restrict__ bias, float* __restrict__ out)
{
    const int e = blockIdx.z;
    const int cnt = g_count[e];
    const int m0 = blockIdx.x * 256;
    if (m0 >= cnt) return;
    const int n0 = blockIdx.y * 128;
    constexpr int NK = KD / 32;

    extern __shared__ char smem_raw[];
    const uint32_t sbase = smem_u32(smem_raw);

    const int tid  = threadIdx.x;
    const int lane = tid & 31;
    const int wid  = tid >> 5;
    const int wm   = wid & 7;
    const int wn   = wid >> 3;

    // ---- loader setup ----
    // A tasks: 256 rows x 4 chunks = 1024 -> 2 per thread (t = tid + 512*i)
    // B tasks: 32 rows x 16 chunks = 512  -> 1 per thread
    const __half* pA[2];
    uint32_t dA[2];
#pragma unroll
    for (int i = 0; i < 2; i++) {
        int t = tid + 512 * i;
        int arow = t >> 2, achunk = t & 3;
        if (G1) {
            int m = m0 + arow;
            int r = (m < cnt) ? g_inv[e * CAP_ + m] : 0;
            pA[i] = g_featr + (size_t)r * KD + achunk * 8;
        } else {
            pA[i] = g_h + ((size_t)e * CAP_ + m0 + arow) * KD + achunk * 8;
        }
        dA[i] = arow * APITCH + achunk * 16;
    }
    const int brow = tid >> 4, bchunk = tid & 15;
    const __half* W = G1 ? g_W1h : g_W2h;
    const __half* pB = W + (size_t)e * KD * ND + (size_t)brow * ND + n0 + bchunk * 8;
    const uint32_t dB = 256 * APITCH + brow * BPITCH + bchunk * 16;

    auto load_stage = [&](int ko, int s) {
        uint32_t st = sbase + s * STAGE_BYTES;
#pragma unroll
        for (int i = 0; i < 2; i++)
            cp_async16(st + dA[i], pA[i] + (size_t)ko * 32);
        cp_async16(st + dB, pB + (size_t)ko * 32 * ND);
        cp_commit();
    };

    load_stage(0, 0); load_stage(1, 1); load_stage(2, 2);

    // ---- ldmatrix lane components ----
    const int a_lmrow = wm * 32 + (lane & 7) + ((lane >> 3) & 1) * 8;
    const int a_kb    = (lane >> 4);
    const int b_k     = (lane & 7) + ((lane >> 3) & 1) * 8;
    const int b_nb    = (lane >> 4) * 8;

    float acc[2][8][4];
#pragma unroll
    for (int im = 0; im < 2; im++)
#pragma unroll
        for (int jn = 0; jn < 8; jn++)
#pragma unroll
            for (int q = 0; q < 4; q++) acc[im][jn][q] = 0.f;

    for (int i = 0; i < NK; i++) {
        if (i <= NK - 3)      cp_wait<2>();
        else if (i == NK - 2) cp_wait<1>();
        else                  cp_wait<0>();
        __syncthreads();
        if (i + 3 < NK) load_stage(i + 3, (i + 3) & 3);

        const uint32_t st = sbase + (i & 3) * STAGE_BYTES;
#pragma unroll
        for (int kk = 0; kk < 2; kk++) {
            uint32_t a[2][4], b[4][4];
#pragma unroll
            for (int im = 0; im < 2; im++)
                ldsm_x4(a[im], st + (a_lmrow + im * 16) * APITCH + (kk * 2 + a_kb) * 16);
#pragma unroll
            for (int j = 0; j < 4; j++)
                ldsm_x4_t(b[j], st + 256 * APITCH + (kk * 16 + b_k) * BPITCH
                                  + (wn * 64 + j * 16 + b_nb) * 2);
#pragma unroll
            for (int im = 0; im < 2; im++)
#pragma unroll
                for (int jn = 0; jn < 8; jn++)
                    mma_f16(acc[im][jn], a[im], b[jn >> 1][(jn & 1) * 2],
                            b[jn >> 1][(jn & 1) * 2 + 1]);
        }
        __syncthreads();
    }

    // ---- epilogue ----
    const int gID = lane >> 2;
    const int tig = lane & 3;
#pragma unroll
    for (int im = 0; im < 2; im++) {
        int r0 = m0 + wm * 32 + im * 16 + gID;
        int r1 = r0 + 8;
        bool v0 = r0 < cnt, v1 = r1 < cnt;
        if (G1) {
            __half* h0 = g_h + ((size_t)e * CAP_ + r0) * ND;
            __half* h1 = g_h + ((size_t)e * CAP_ + r1) * ND;
#pragma unroll
            for (int jn = 0; jn < 8; jn++) {
                int c = n0 + wn * 64 + jn * 8 + tig * 2;
                float bx = bias[c], by = bias[c + 1];
                if (v0) {
                    __half2 h = __floats2half2_rn(fmaxf(acc[im][jn][0] + bx, 0.f),
                                                  fmaxf(acc[im][jn][1] + by, 0.f));
                    *reinterpret_cast<__half2*>(h0 + c) = h;
                }
                if (v1) {
                    __half2 h = __floats2half2_rn(fmaxf(acc[im][jn][2] + bx, 0.f),
                                                  fmaxf(acc[im][jn][3] + by, 0.f));
                    *reinterpret_cast<__half2*>(h1 + c) = h;
                }
            }
        } else {
            int   i0 = v0 ? g_inv[e * CAP_ + r0] : 0;
            int   i1 = v1 ? g_inv[e * CAP_ + r1] : 0;
            float w0 = v0 ? g_wslot[e * CAP_ + r0] : 0.f;
            float w1 = v1 ? g_wslot[e * CAP_ + r1] : 0.f;
#pragma unroll
            for (int jn = 0; jn < 8; jn++) {
                int c = n0 + wn * 64 + jn * 8 + tig * 2;
                float bx = bias[c], by = bias[c + 1];
                if (v0) {
                    atomicAdd(out + (size_t)i0 * ND + c,     w0 * (acc[im][jn][0] + bx));
                    atomicAdd(out + (size_t)i0 * ND + c + 1, w0 * (acc[im][jn][1] + by));
                }
                if (v1) {
                    atomicAdd(out + (size_t)i1 * ND + c,     w1 * (acc[im][jn][2] + bx));
                    atomicAdd(out + (size_t)i1 * ND + c + 1, w1 * (acc[im][jn][3] + by));
                }
            }
        }
    }
}

// ---------------- launch ------------------------------------------------------
extern "C" void kernel_launch(void* const* d_in, const int* in_sizes, int n_in,
                              void* d_out, int out_size)
{
    const float* features = (const float*)d_in[0];
    const float* Wg       = (const float*)d_in[1];
    const float* bg       = (const float*)d_in[2];
    const float* W1       = (const float*)d_in[3];
    const float* b1       = (const float*)d_in[4];
    const float* W2       = (const float*)d_in[5];
    const float* b2       = (const float*)d_in[6];
    const float* ebias    = (const float*)d_in[7];
    float* out = (float*)d_out;

    cudaFuncSetAttribute(moe_gemm<F_, H_, true>,
                         cudaFuncAttributeMaxDynamicSharedMemorySize, SMEM_TOTAL);
    cudaFuncSetAttribute(moe_gemm<H_, O_, false>,
                         cudaFuncAttributeMaxDynamicSharedMemorySize, SMEM_TOTAL);

    cudaMemsetAsync(out, 0, (size_t)B_ * O_ * sizeof(float), 0);

    __half* d_featr; cudaGetSymbolAddress((void**)&d_featr, g_featr);
    __half* d_W1h;   cudaGetSymbolAddress((void**)&d_W1h, g_W1h);
    __half* d_W2h;   cudaGetSymbolAddress((void**)&d_W2h, g_W2h);

    f2h_kernel<<<(B_ * F_ / 4) / 256, 256>>>(features, d_featr);
    f2h_kernel<<<((size_t)E_ * F_ * H_ / 4) / 256, 256>>>(W1, d_W1h);
    f2h_kernel<<<((size_t)E_ * H_ * O_ / 4) / 256, 256>>>(W2, d_W2h);
    gating_kernel<<<B_ / 8, 256>>>(features, Wg, bg, ebias);
    scan_kernel<<<1, 512>>>();

    moe_gemm<F_, H_, true ><<<dim3(CAP_ / 256, H_ / 128, E_), 512, SMEM_TOTAL>>>(b1, nullptr);
    moe_gemm<H_, O_, false><<<dim3(CAP_ / 256, O_ / 128, E_), 512, SMEM_TOTAL>>>(b2, out);
}

// round 5
// speedup vs baseline: 1.7606x; 1.0131x over previous
#include <cuda_runtime.h>
#include <cuda_fp16.h>
#include <math.h>
#include <stdint.h>

// Problem constants
#define B_   16384
#define F_   1024
#define H_   4096
#define O_   1024
#define E_   16
#define CAP_ 2560   // ceil(1.25 * B * 2 / 16)

// ---------------- scratch (device globals; no allocation allowed) ----------
__device__ __half  g_h[(size_t)E_ * CAP_ * H_];     // expert hidden activations (fp16)
__device__ __half  g_featr[(size_t)B_ * F_];        // features in fp16
__device__ __half  g_W1h[(size_t)E_ * F_ * H_];     // W1 in fp16
__device__ __half  g_W2h[(size_t)E_ * H_ * O_];     // W2 in fp16
__device__ int     g_inv[E_ * CAP_];
__device__ float   g_wslot[E_ * CAP_];
__device__ int     g_count[E_];
__device__ int2    g_route_e[B_];
__device__ float2  g_route_w[B_];

// ---------------- helpers ---------------------------------------------------
__device__ __forceinline__ uint32_t smem_u32(const void* p) {
    uint32_t a;
    asm("{ .reg .u64 t; cvta.to.shared.u64 t, %1; cvt.u32.u64 %0, t; }" : "=r"(a) : "l"(p));
    return a;
}
__device__ __forceinline__ void cp_async16(uint32_t dst, const void* src) {
    asm volatile("cp.async.cg.shared.global [%0], [%1], 16;" :: "r"(dst), "l"(src));
}
__device__ __forceinline__ void cp_commit() { asm volatile("cp.async.commit_group;" ::: "memory"); }
template<int N> __device__ __forceinline__ void cp_wait() {
    asm volatile("cp.async.wait_group %0;" :: "n"(N) : "memory");
}
__device__ __forceinline__ void ldsm_x4(uint32_t r[4], uint32_t addr) {
    asm volatile("ldmatrix.sync.aligned.m8n8.x4.shared.b16 {%0,%1,%2,%3}, [%4];"
                 : "=r"(r[0]), "=r"(r[1]), "=r"(r[2]), "=r"(r[3]) : "r"(addr));
}
__device__ __forceinline__ void ldsm_x4_t(uint32_t r[4], uint32_t addr) {
    asm volatile("ldmatrix.sync.aligned.m8n8.x4.trans.shared.b16 {%0,%1,%2,%3}, [%4];"
                 : "=r"(r[0]), "=r"(r[1]), "=r"(r[2]), "=r"(r[3]) : "r"(addr));
}
__device__ __forceinline__ void mma_f16(float c[4], const uint32_t a[4],
                                        uint32_t b0, uint32_t b1) {
    asm volatile(
        "mma.sync.aligned.m16n8k16.row.col.f32.f16.f16.f32 "
        "{%0,%1,%2,%3}, {%4,%5,%6,%7}, {%8,%9}, {%0,%1,%2,%3};"
        : "+f"(c[0]), "+f"(c[1]), "+f"(c[2]), "+f"(c[3])
        : "r"(a[0]), "r"(a[1]), "r"(a[2]), "r"(a[3]), "r"(b0), "r"(b1));
}

// ---------------- fp32 -> fp16 conversion ------------------------------------
__global__ __launch_bounds__(256) void f2h_kernel(const float* __restrict__ src,
                                                  __half* __restrict__ dst)
{
    size_t i = (size_t)blockIdx.x * 256 + threadIdx.x;   // float4 index
    float4 v = reinterpret_cast<const float4*>(src)[i];
    __half2 h0 = __floats2half2_rn(v.x, v.y);
    __half2 h1 = __floats2half2_rn(v.z, v.w);
    reinterpret_cast<__half2*>(dst)[2 * i]     = h0;
    reinterpret_cast<__half2*>(dst)[2 * i + 1] = h1;
}

// ---------------- gating (+ fused feature fp16 conversion) -------------------
__global__ __launch_bounds__(256) void gating_kernel(
    const float* __restrict__ features,
    const float* __restrict__ Wg,
    const float* __restrict__ bg,
    const float* __restrict__ ebias,
    __half* __restrict__ featr)
{
    int warp = threadIdx.x >> 5;
    int lane = threadIdx.x & 31;
    int b = blockIdx.x * 8 + warp;
    if (b >= B_) return;

    const float4* f4 = reinterpret_cast<const float4*>(features + (size_t)b * F_);
    __half2* h2 = reinterpret_cast<__half2*>(featr + (size_t)b * F_);
    float acc[E_];
#pragma unroll
    for (int e = 0; e < E_; e++) acc[e] = 0.f;

    for (int k4 = lane; k4 < F_ / 4; k4 += 32) {
        float4 fv = f4[k4];
        h2[2 * k4]     = __floats2half2_rn(fv.x, fv.y);
        h2[2 * k4 + 1] = __floats2half2_rn(fv.z, fv.w);
#pragma unroll
        for (int e = 0; e < E_; e++) {
            float4 wv = reinterpret_cast<const float4*>(Wg + (size_t)e * F_)[k4];
            acc[e] += fv.x * wv.x + fv.y * wv.y + fv.z * wv.z + fv.w * wv.w;
        }
    }
#pragma unroll
    for (int e = 0; e < E_; e++) {
#pragma unroll
        for (int off = 16; off > 0; off >>= 1)
            acc[e] += __shfl_xor_sync(0xFFFFFFFFu, acc[e], off);
    }
    if (lane == 0) {
        float s[E_];
#pragma unroll
        for (int e = 0; e < E_; e++) s[e] = acc[e] + bg[e] + ebias[e];
        int e0 = 0; float s0 = s[0];
#pragma unroll
        for (int e = 1; e < E_; e++) if (s[e] > s0) { s0 = s[e]; e0 = e; }
        int e1 = -1; float s1 = -3.402823e38f;
#pragma unroll
        for (int e = 0; e < E_; e++) if (e != e0 && s[e] > s1) { s1 = s[e]; e1 = e; }
        float z = expf(s1 - s0);
        float w0 = 1.f / (1.f + z);
        float w1 = z / (1.f + z);
        g_route_e[b] = make_int2(e0, e1);
        g_route_w[b] = make_float2(w0, w1);
    }
}

// ---------------- deterministic capacity scan -------------------------------
__global__ __launch_bounds__(512) void scan_kernel()
{
    int e = threadIdx.x >> 5;
    int lane = threadIdx.x & 31;
    int base = 0;
    for (int start = 0; start < B_; start += 32) {
        int b = start + lane;
        int2 re = g_route_e[b];
        bool asg = (re.x == e) || (re.y == e);
        unsigned mask = __ballot_sync(0xFFFFFFFFu, asg);
        int pos = base + __popc(mask & ((1u << lane) - 1u));
        if (asg && pos < CAP_) {
            float2 rw = g_route_w[b];
            g_inv[e * CAP_ + pos] = b;
            g_wslot[e * CAP_ + pos] = (re.x == e) ? rw.x : rw.y;
        }
        base += __popc(mask);
    }
    if (lane == 0) g_count[e] = base < CAP_ ? base : CAP_;
}

// ---------------- fp16 tensor-core grouped GEMM ------------------------------
// CTA tile 256(m) x 128(n), BK=32, 5-stage cp.async pipeline, 512 threads.
// 16 warps: wm = wid&7 (8 m-warps of 32 rows), wn = wid>>3 (2 n-warps of 64).
// ONE __syncthreads per k-iteration (refill target == stage consumed last iter).
#define APITCH 80
#define BPITCH 272
#define STAGE_BYTES (256 * APITCH + 32 * BPITCH)   // 29184
#define NSTAGE 5
#define SMEM_TOTAL (NSTAGE * STAGE_BYTES)          // 145920

template<int KD, int ND, bool G1>
__global__ __launch_bounds__(512, 1) void moe_gemm(
    const float* __restrict__ bias, float* __restrict__ out)
{
    const int e = blockIdx.z;
    const int cnt = g_count[e];
    const int m0 = blockIdx.x * 256;
    if (m0 >= cnt) return;
    const int n0 = blockIdx.y * 128;
    constexpr int NK = KD / 32;

    extern __shared__ char smem_raw[];
    const uint32_t sbase = smem_u32(smem_raw);

    const int tid  = threadIdx.x;
    const int lane = tid & 31;
    const int wid  = tid >> 5;
    const int wm   = wid & 7;
    const int wn   = wid >> 3;

    // ---- loader setup ----
    const __half* pA[2];
    uint32_t dA[2];
#pragma unroll
    for (int i = 0; i < 2; i++) {
        int t = tid + 512 * i;
        int arow = t >> 2, achunk = t & 3;
        if (G1) {
            int m = m0 + arow;
            int r = (m < cnt) ? g_inv[e * CAP_ + m] : 0;
            pA[i] = g_featr + (size_t)r * KD + achunk * 8;
        } else {
            pA[i] = g_h + ((size_t)e * CAP_ + m0 + arow) * KD + achunk * 8;
        }
        dA[i] = arow * APITCH + achunk * 16;
    }
    const int brow = tid >> 4, bchunk = tid & 15;
    const __half* W = G1 ? g_W1h : g_W2h;
    const __half* pB = W + (size_t)e * KD * ND + (size_t)brow * ND + n0 + bchunk * 8;
    const uint32_t dB = 256 * APITCH + brow * BPITCH + bchunk * 16;

    auto load_stage = [&](int ko, int s) {
        uint32_t st = sbase + s * STAGE_BYTES;
#pragma unroll
        for (int i = 0; i < 2; i++)
            cp_async16(st + dA[i], pA[i] + (size_t)ko * 32);
        cp_async16(st + dB, pB + (size_t)ko * 32 * ND);
        cp_commit();
    };

    load_stage(0, 0); load_stage(1, 1); load_stage(2, 2); load_stage(3, 3);

    // ---- ldmatrix lane components ----
    const int a_lmrow = wm * 32 + (lane & 7) + ((lane >> 3) & 1) * 8;
    const int a_kb    = (lane >> 4);
    const int b_k     = (lane & 7) + ((lane >> 3) & 1) * 8;
    const int b_nb    = (lane >> 4) * 8;

    float acc[2][8][4];
#pragma unroll
    for (int im = 0; im < 2; im++)
#pragma unroll
        for (int jn = 0; jn < 8; jn++)
#pragma unroll
            for (int q = 0; q < 4; q++) acc[im][jn][q] = 0.f;

    int s_cur = 0;          // i % 5
    int s_load = 4;         // (i+4) % 5
    for (int i = 0; i < NK; i++) {
        if (i <= NK - 4)      cp_wait<3>();
        else if (i == NK - 3) cp_wait<2>();
        else if (i == NK - 2) cp_wait<1>();
        else                  cp_wait<0>();
        __syncthreads();
        // refill target (i+4)%5 == (i-1)%5: consumed last iter; barrier above
        // guarantees all warps are past it.
        if (i + 4 < NK) load_stage(i + 4, s_load);

        const uint32_t st = sbase + s_cur * STAGE_BYTES;
#pragma unroll
        for (int kk = 0; kk < 2; kk++) {
            uint32_t a[2][4], b[4][4];
#pragma unroll
            for (int im = 0; im < 2; im++)
                ldsm_x4(a[im], st + (a_lmrow + im * 16) * APITCH + (kk * 2 + a_kb) * 16);
#pragma unroll
            for (int j = 0; j < 4; j++)
                ldsm_x4_t(b[j], st + 256 * APITCH + (kk * 16 + b_k) * BPITCH
                                  + (wn * 64 + j * 16 + b_nb) * 2);
#pragma unroll
            for (int im = 0; im < 2; im++)
#pragma unroll
                for (int jn = 0; jn < 8; jn++)
                    mma_f16(acc[im][jn], a[im], b[jn >> 1][(jn & 1) * 2],
                            b[jn >> 1][(jn & 1) * 2 + 1]);
        }
        if (++s_cur == NSTAGE) s_cur = 0;
        if (++s_load == NSTAGE) s_load = 0;
    }

    // ---- epilogue ----
    const int gID = lane >> 2;
    const int tig = lane & 3;
#pragma unroll
    for (int im = 0; im < 2; im++) {
        int r0 = m0 + wm * 32 + im * 16 + gID;
        int r1 = r0 + 8;
        bool v0 = r0 < cnt, v1 = r1 < cnt;
        if (G1) {
            __half* h0 = g_h + ((size_t)e * CAP_ + r0) * ND;
            __half* h1 = g_h + ((size_t)e * CAP_ + r1) * ND;
#pragma unroll
            for (int jn = 0; jn < 8; jn++) {
                int c = n0 + wn * 64 + jn * 8 + tig * 2;
                float bx = bias[c], by = bias[c + 1];
                if (v0) {
                    __half2 h = __floats2half2_rn(fmaxf(acc[im][jn][0] + bx, 0.f),
                                                  fmaxf(acc[im][jn][1] + by, 0.f));
                    *reinterpret_cast<__half2*>(h0 + c) = h;
                }
                if (v1) {
                    __half2 h = __floats2half2_rn(fmaxf(acc[im][jn][2] + bx, 0.f),
                                                  fmaxf(acc[im][jn][3] + by, 0.f));
                    *reinterpret_cast<__half2*>(h1 + c) = h;
                }
            }
        } else {
            int   i0 = v0 ? g_inv[e * CAP_ + r0] : 0;
            int   i1 = v1 ? g_inv[e * CAP_ + r1] : 0;
            float w0 = v0 ? g_wslot[e * CAP_ + r0] : 0.f;
            float w1 = v1 ? g_wslot[e * CAP_ + r1] : 0.f;
#pragma unroll
            for (int jn = 0; jn < 8; jn++) {
                int c = n0 + wn * 64 + jn * 8 + tig * 2;
                float bx = bias[c], by = bias[c + 1];
                if (v0) {
                    atomicAdd(out + (size_t)i0 * ND + c,     w0 * (acc[im][jn][0] + bx));
                    atomicAdd(out + (size_t)i0 * ND + c + 1, w0 * (acc[im][jn][1] + by));
                }
                if (v1) {
                    atomicAdd(out + (size_t)i1 * ND + c,     w1 * (acc[im][jn][2] + bx));
                    atomicAdd(out + (size_t)i1 * ND + c + 1, w1 * (acc[im][jn][3] + by));
                }
            }
        }
    }
}

// ---------------- launch ------------------------------------------------------
extern "C" void kernel_launch(void* const* d_in, const int* in_sizes, int n_in,
                              void* d_out, int out_size)
{
    const float* features = (const float*)d_in[0];
    const float* Wg       = (const float*)d_in[1];
    const float* bg       = (const float*)d_in[2];
    const float* W1       = (const float*)d_in[3];
    const float* b1       = (const float*)d_in[4];
    const float* W2       = (const float*)d_in[5];
    const float* b2       = (const float*)d_in[6];
    const float* ebias    = (const float*)d_in[7];
    float* out = (float*)d_out;

    cudaFuncSetAttribute(moe_gemm<F_, H_, true>,
                         cudaFuncAttributeMaxDynamicSharedMemorySize, SMEM_TOTAL);
    cudaFuncSetAttribute(moe_gemm<H_, O_, false>,
                         cudaFuncAttributeMaxDynamicSharedMemorySize, SMEM_TOTAL);

    cudaMemsetAsync(out, 0, (size_t)B_ * O_ * sizeof(float), 0);

    __half* d_featr; cudaGetSymbolAddress((void**)&d_featr, g_featr);
    __half* d_W1h;   cudaGetSymbolAddress((void**)&d_W1h, g_W1h);
    __half* d_W2h;   cudaGetSymbolAddress((void**)&d_W2h, g_W2h);

    f2h_kernel<<<((size_t)E_ * F_ * H_ / 4) / 256, 256>>>(W1, d_W1h);
    f2h_kernel<<<((size_t)E_ * H_ * O_ / 4) / 256, 256>>>(W2, d_W2h);
    gating_kernel<<<B_ / 8, 256>>>(features, Wg, bg, ebias, d_featr);
    scan_kernel<<<1, 512>>>();

    moe_gemm<F_, H_, true ><<<dim3(CAP_ / 256, H_ / 128, E_), 512, SMEM_TOTAL>>>(b1, nullptr);
    moe_gemm<H_, O_, false><<<dim3(CAP_ / 256, O_ / 128, E_), 512, SMEM_TOTAL>>>(b2, out);
}

// round 6
// speedup vs baseline: 1.9384x; 1.1010x over previous
#include <cuda_runtime.h>
#include <cuda_fp16.h>
#include <math.h>
#include <stdint.h>

// Problem constants
#define B_   16384
#define F_   1024
#define H_   4096
#define O_   1024
#define E_   16
#define CAP_ 2560   // ceil(1.25 * B * 2 / 16)

// ---------------- scratch (device globals; no allocation allowed) ----------
__device__ __half  g_h[(size_t)E_ * CAP_ * H_];     // expert hidden activations (fp16)
__device__ __half  g_featr[(size_t)B_ * F_];        // features in fp16
__device__ __half  g_W1h[(size_t)E_ * F_ * H_];     // W1 in fp16
__device__ __half  g_W2h[(size_t)E_ * H_ * O_];     // W2 in fp16
__device__ int     g_inv[E_ * CAP_];
__device__ float   g_wslot[E_ * CAP_];
__device__ int     g_count[E_];
__device__ int2    g_route_e[B_];
__device__ float2  g_route_w[B_];

// ---------------- helpers ---------------------------------------------------
__device__ __forceinline__ uint32_t smem_u32(const void* p) {
    uint32_t a;
    asm("{ .reg .u64 t; cvta.to.shared.u64 t, %1; cvt.u32.u64 %0, t; }" : "=r"(a) : "l"(p));
    return a;
}
__device__ __forceinline__ void cp_async16(uint32_t dst, const void* src) {
    asm volatile("cp.async.cg.shared.global [%0], [%1], 16;" :: "r"(dst), "l"(src));
}
__device__ __forceinline__ void cp_commit() { asm volatile("cp.async.commit_group;" ::: "memory"); }
template<int N> __device__ __forceinline__ void cp_wait() {
    asm volatile("cp.async.wait_group %0;" :: "n"(N) : "memory");
}
__device__ __forceinline__ void ldsm_x4(uint32_t r[4], uint32_t addr) {
    asm volatile("ldmatrix.sync.aligned.m8n8.x4.shared.b16 {%0,%1,%2,%3}, [%4];"
                 : "=r"(r[0]), "=r"(r[1]), "=r"(r[2]), "=r"(r[3]) : "r"(addr));
}
__device__ __forceinline__ void ldsm_x4_t(uint32_t r[4], uint32_t addr) {
    asm volatile("ldmatrix.sync.aligned.m8n8.x4.trans.shared.b16 {%0,%1,%2,%3}, [%4];"
                 : "=r"(r[0]), "=r"(r[1]), "=r"(r[2]), "=r"(r[3]) : "r"(addr));
}
__device__ __forceinline__ void mma_f16(float c[4], const uint32_t a[4],
                                        uint32_t b0, uint32_t b1) {
    asm volatile(
        "mma.sync.aligned.m16n8k16.row.col.f32.f16.f16.f32 "
        "{%0,%1,%2,%3}, {%4,%5,%6,%7}, {%8,%9}, {%0,%1,%2,%3};"
        : "+f"(c[0]), "+f"(c[1]), "+f"(c[2]), "+f"(c[3])
        : "r"(a[0]), "r"(a[1]), "r"(a[2]), "r"(a[3]), "r"(b0), "r"(b1));
}

// ---------------- fp32 -> fp16 conversion ------------------------------------
__global__ __launch_bounds__(256) void f2h_kernel(const float* __restrict__ src,
                                                  __half* __restrict__ dst)
{
    size_t i = (size_t)blockIdx.x * 256 + threadIdx.x;   // float4 index
    float4 v = reinterpret_cast<const float4*>(src)[i];
    __half2 h0 = __floats2half2_rn(v.x, v.y);
    __half2 h1 = __floats2half2_rn(v.z, v.w);
    reinterpret_cast<__half2*>(dst)[2 * i]     = h0;
    reinterpret_cast<__half2*>(dst)[2 * i + 1] = h1;
}

// ---------------- gating (+ fused feature fp16 conversion) -------------------
__global__ __launch_bounds__(256) void gating_kernel(
    const float* __restrict__ features,
    const float* __restrict__ Wg,
    const float* __restrict__ bg,
    const float* __restrict__ ebias,
    __half* __restrict__ featr)
{
    int warp = threadIdx.x >> 5;
    int lane = threadIdx.x & 31;
    int b = blockIdx.x * 8 + warp;
    if (b >= B_) return;

    const float4* f4 = reinterpret_cast<const float4*>(features + (size_t)b * F_);
    __half2* h2 = reinterpret_cast<__half2*>(featr + (size_t)b * F_);
    float acc[E_];
#pragma unroll
    for (int e = 0; e < E_; e++) acc[e] = 0.f;

    for (int k4 = lane; k4 < F_ / 4; k4 += 32) {
        float4 fv = f4[k4];
        h2[2 * k4]     = __floats2half2_rn(fv.x, fv.y);
        h2[2 * k4 + 1] = __floats2half2_rn(fv.z, fv.w);
#pragma unroll
        for (int e = 0; e < E_; e++) {
            float4 wv = reinterpret_cast<const float4*>(Wg + (size_t)e * F_)[k4];
            acc[e] += fv.x * wv.x + fv.y * wv.y + fv.z * wv.z + fv.w * wv.w;
        }
    }
#pragma unroll
    for (int e = 0; e < E_; e++) {
#pragma unroll
        for (int off = 16; off > 0; off >>= 1)
            acc[e] += __shfl_xor_sync(0xFFFFFFFFu, acc[e], off);
    }
    if (lane == 0) {
        float s[E_];
#pragma unroll
        for (int e = 0; e < E_; e++) s[e] = acc[e] + bg[e] + ebias[e];
        int e0 = 0; float s0 = s[0];
#pragma unroll
        for (int e = 1; e < E_; e++) if (s[e] > s0) { s0 = s[e]; e0 = e; }
        int e1 = -1; float s1 = -3.402823e38f;
#pragma unroll
        for (int e = 0; e < E_; e++) if (e != e0 && s[e] > s1) { s1 = s[e]; e1 = e; }
        float z = expf(s1 - s0);
        float w0 = 1.f / (1.f + z);
        float w1 = z / (1.f + z);
        g_route_e[b] = make_int2(e0, e1);
        g_route_w[b] = make_float2(w0, w1);
    }
}

// ---------------- parallel capacity scan: one block per expert ---------------
// 1024 threads = 32 warps; each iteration covers 1024 consecutive rows.
// Ordered prefix: per-warp ballot popc + cross-warp smem prefix.
__global__ __launch_bounds__(1024) void scan_kernel()
{
    const int e = blockIdx.x;
    const int tid = threadIdx.x;
    const int lane = tid & 31;
    const int wid = tid >> 5;
    __shared__ int warp_cnt[32];

    int base = 0;
    for (int start = 0; start < B_; start += 1024) {
        int b = start + tid;
        int2 re = g_route_e[b];
        bool asg = (re.x == e) || (re.y == e);
        unsigned mask = __ballot_sync(0xFFFFFFFFu, asg);
        int lane_pos = __popc(mask & ((1u << lane) - 1u));
        if (lane == 0) warp_cnt[wid] = __popc(mask);
        __syncthreads();
        int wbase = 0, tot = 0;
#pragma unroll
        for (int j = 0; j < 32; j++) {
            int c = warp_cnt[j];
            if (j < wid) wbase += c;
            tot += c;
        }
        int pos = base + wbase + lane_pos;
        if (asg && pos < CAP_) {
            float2 rw = g_route_w[b];
            g_inv[e * CAP_ + pos] = b;
            g_wslot[e * CAP_ + pos] = (re.x == e) ? rw.x : rw.y;
        }
        base += tot;
        __syncthreads();
    }
    if (tid == 0) g_count[e] = base < CAP_ ? base : CAP_;
}

// ---------------- fp16 tensor-core grouped GEMM ------------------------------
// CTA tile 256(m) x 128(n), BK=32, 5-stage cp.async pipeline, 512 threads.
#define APITCH 80
#define BPITCH 272
#define STAGE_BYTES (256 * APITCH + 32 * BPITCH)   // 29184
#define NSTAGE 5
#define SMEM_TOTAL (NSTAGE * STAGE_BYTES)          // 145920

template<int KD, int ND, bool G1>
__global__ __launch_bounds__(512, 1) void moe_gemm(
    const float* __restrict__ bias, float* __restrict__ out)
{
    const int e = blockIdx.z;
    const int cnt = g_count[e];
    const int m0 = blockIdx.x * 256;
    if (m0 >= cnt) return;
    const int n0 = blockIdx.y * 128;
    constexpr int NK = KD / 32;

    extern __shared__ char smem_raw[];
    const uint32_t sbase = smem_u32(smem_raw);

    const int tid  = threadIdx.x;
    const int lane = tid & 31;
    const int wid  = tid >> 5;
    const int wm   = wid & 7;
    const int wn   = wid >> 3;

    // ---- loader setup ----
    const __half* pA[2];
    uint32_t dA[2];
#pragma unroll
    for (int i = 0; i < 2; i++) {
        int t = tid + 512 * i;
        int arow = t >> 2, achunk = t & 3;
        if (G1) {
            int m = m0 + arow;
            int r = (m < cnt) ? g_inv[e * CAP_ + m] : 0;
            pA[i] = g_featr + (size_t)r * KD + achunk * 8;
        } else {
            pA[i] = g_h + ((size_t)e * CAP_ + m0 + arow) * KD + achunk * 8;
        }
        dA[i] = arow * APITCH + achunk * 16;
    }
    const int brow = tid >> 4, bchunk = tid & 15;
    const __half* W = G1 ? g_W1h : g_W2h;
    const __half* pB = W + (size_t)e * KD * ND + (size_t)brow * ND + n0 + bchunk * 8;
    const uint32_t dB = 256 * APITCH + brow * BPITCH + bchunk * 16;

    auto load_stage = [&](int ko, int s) {
        uint32_t st = sbase + s * STAGE_BYTES;
#pragma unroll
        for (int i = 0; i < 2; i++)
            cp_async16(st + dA[i], pA[i] + (size_t)ko * 32);
        cp_async16(st + dB, pB + (size_t)ko * 32 * ND);
        cp_commit();
    };

    load_stage(0, 0); load_stage(1, 1); load_stage(2, 2); load_stage(3, 3);

    // ---- ldmatrix lane components ----
    const int a_lmrow = wm * 32 + (lane & 7) + ((lane >> 3) & 1) * 8;
    const int a_kb    = (lane >> 4);
    const int b_k     = (lane & 7) + ((lane >> 3) & 1) * 8;
    const int b_nb    = (lane >> 4) * 8;

    float acc[2][8][4];
#pragma unroll
    for (int im = 0; im < 2; im++)
#pragma unroll
        for (int jn = 0; jn < 8; jn++)
#pragma unroll
            for (int q = 0; q < 4; q++) acc[im][jn][q] = 0.f;

    int s_cur = 0;          // i % 5
    int s_load = 4;         // (i+4) % 5
    for (int i = 0; i < NK; i++) {
        if (i <= NK - 4)      cp_wait<3>();
        else if (i == NK - 3) cp_wait<2>();
        else if (i == NK - 2) cp_wait<1>();
        else                  cp_wait<0>();
        __syncthreads();
        // refill target (i+4)%5 == (i-1)%5: consumed last iter; barrier above
        // guarantees all warps are past it.
        if (i + 4 < NK) load_stage(i + 4, s_load);

        const uint32_t st = sbase + s_cur * STAGE_BYTES;
#pragma unroll
        for (int kk = 0; kk < 2; kk++) {
            uint32_t a[2][4], b[4][4];
#pragma unroll
            for (int im = 0; im < 2; im++)
                ldsm_x4(a[im], st + (a_lmrow + im * 16) * APITCH + (kk * 2 + a_kb) * 16);
#pragma unroll
            for (int j = 0; j < 4; j++)
                ldsm_x4_t(b[j], st + 256 * APITCH + (kk * 16 + b_k) * BPITCH
                                  + (wn * 64 + j * 16 + b_nb) * 2);
#pragma unroll
            for (int im = 0; im < 2; im++)
#pragma unroll
                for (int jn = 0; jn < 8; jn++)
                    mma_f16(acc[im][jn], a[im], b[jn >> 1][(jn & 1) * 2],
                            b[jn >> 1][(jn & 1) * 2 + 1]);
        }
        if (++s_cur == NSTAGE) s_cur = 0;
        if (++s_load == NSTAGE) s_load = 0;
    }

    // ---- epilogue ----
    const int gID = lane >> 2;
    const int tig = lane & 3;
#pragma unroll
    for (int im = 0; im < 2; im++) {
        int r0 = m0 + wm * 32 + im * 16 + gID;
        int r1 = r0 + 8;
        bool v0 = r0 < cnt, v1 = r1 < cnt;
        if (G1) {
            __half* h0 = g_h + ((size_t)e * CAP_ + r0) * ND;
            __half* h1 = g_h + ((size_t)e * CAP_ + r1) * ND;
#pragma unroll
            for (int jn = 0; jn < 8; jn++) {
                int c = n0 + wn * 64 + jn * 8 + tig * 2;
                float bx = bias[c], by = bias[c + 1];
                if (v0) {
                    __half2 h = __floats2half2_rn(fmaxf(acc[im][jn][0] + bx, 0.f),
                                                  fmaxf(acc[im][jn][1] + by, 0.f));
                    *reinterpret_cast<__half2*>(h0 + c) = h;
                }
                if (v1) {
                    __half2 h = __floats2half2_rn(fmaxf(acc[im][jn][2] + bx, 0.f),
                                                  fmaxf(acc[im][jn][3] + by, 0.f));
                    *reinterpret_cast<__half2*>(h1 + c) = h;
                }
            }
        } else {
            int   i0 = v0 ? g_inv[e * CAP_ + r0] : 0;
            int   i1 = v1 ? g_inv[e * CAP_ + r1] : 0;
            float w0 = v0 ? g_wslot[e * CAP_ + r0] : 0.f;
            float w1 = v1 ? g_wslot[e * CAP_ + r1] : 0.f;
#pragma unroll
            for (int jn = 0; jn < 8; jn++) {
                int c = n0 + wn * 64 + jn * 8 + tig * 2;
                float bx = bias[c], by = bias[c + 1];
                if (v0) {
                    atomicAdd(out + (size_t)i0 * ND + c,     w0 * (acc[im][jn][0] + bx));
                    atomicAdd(out + (size_t)i0 * ND + c + 1, w0 * (acc[im][jn][1] + by));
                }
                if (v1) {
                    atomicAdd(out + (size_t)i1 * ND + c,     w1 * (acc[im][jn][2] + bx));
                    atomicAdd(out + (size_t)i1 * ND + c + 1, w1 * (acc[im][jn][3] + by));
                }
            }
        }
    }
}

// ---------------- launch ------------------------------------------------------
extern "C" void kernel_launch(void* const* d_in, const int* in_sizes, int n_in,
                              void* d_out, int out_size)
{
    const float* features = (const float*)d_in[0];
    const float* Wg       = (const float*)d_in[1];
    const float* bg       = (const float*)d_in[2];
    const float* W1       = (const float*)d_in[3];
    const float* b1       = (const float*)d_in[4];
    const float* W2       = (const float*)d_in[5];
    const float* b2       = (const float*)d_in[6];
    const float* ebias    = (const float*)d_in[7];
    float* out = (float*)d_out;

    cudaFuncSetAttribute(moe_gemm<F_, H_, true>,
                         cudaFuncAttributeMaxDynamicSharedMemorySize, SMEM_TOTAL);
    cudaFuncSetAttribute(moe_gemm<H_, O_, false>,
                         cudaFuncAttributeMaxDynamicSharedMemorySize, SMEM_TOTAL);

    cudaMemsetAsync(out, 0, (size_t)B_ * O_ * sizeof(float), 0);

    __half* d_featr; cudaGetSymbolAddress((void**)&d_featr, g_featr);
    __half* d_W1h;   cudaGetSymbolAddress((void**)&d_W1h, g_W1h);
    __half* d_W2h;   cudaGetSymbolAddress((void**)&d_W2h, g_W2h);

    f2h_kernel<<<((size_t)E_ * F_ * H_ / 4) / 256, 256>>>(W1, d_W1h);
    f2h_kernel<<<((size_t)E_ * H_ * O_ / 4) / 256, 256>>>(W2, d_W2h);
    gating_kernel<<<B_ / 8, 256>>>(features, Wg, bg, ebias, d_featr);
    scan_kernel<<<E_, 1024>>>();

    moe_gemm<F_, H_, true ><<<dim3(CAP_ / 256, H_ / 128, E_), 512, SMEM_TOTAL>>>(b1, nullptr);
    moe_gemm<H_, O_, false><<<dim3(CAP_ / 256, O_ / 128, E_), 512, SMEM_TOTAL>>>(b2, out);
}

// round 7
// speedup vs baseline: 2.2124x; 1.1414x over previous
#include <cuda_runtime.h>
#include <cuda_fp16.h>
#include <math.h>
#include <stdint.h>

// Problem constants
#define B_   16384
#define F_   1024
#define H_   4096
#define O_   1024
#define E_   16
#define CAP_ 2560   // ceil(1.25 * B * 2 / 16)

// ---------------- scratch (device globals; no allocation allowed) ----------
__device__ __half  g_h[(size_t)E_ * CAP_ * H_];     // expert hidden activations (fp16)
__device__ __half  g_featr[(size_t)B_ * F_];        // features in fp16
__device__ __half  g_W1h[(size_t)E_ * F_ * H_];     // W1 in fp16
__device__ __half  g_W2h[(size_t)E_ * H_ * O_];     // W2 in fp16
__device__ int     g_inv[E_ * CAP_];
__device__ float   g_wslot[E_ * CAP_];
__device__ int     g_count[E_];
__device__ int2    g_route_e[B_];
__device__ float2  g_route_w[B_];

// ---------------- helpers ---------------------------------------------------
__device__ __forceinline__ uint32_t smem_u32(const void* p) {
    uint32_t a;
    asm("{ .reg .u64 t; cvta.to.shared.u64 t, %1; cvt.u32.u64 %0, t; }" : "=r"(a) : "l"(p));
    return a;
}
__device__ __forceinline__ void cp_async16(uint32_t dst, const void* src) {
    asm volatile("cp.async.cg.shared.global [%0], [%1], 16;" :: "r"(dst), "l"(src));
}
__device__ __forceinline__ void cp_commit() { asm volatile("cp.async.commit_group;" ::: "memory"); }
template<int N> __device__ __forceinline__ void cp_wait() {
    asm volatile("cp.async.wait_group %0;" :: "n"(N) : "memory");
}
__device__ __forceinline__ void ldsm_x4(uint32_t r[4], uint32_t addr) {
    asm volatile("ldmatrix.sync.aligned.m8n8.x4.shared.b16 {%0,%1,%2,%3}, [%4];"
                 : "=r"(r[0]), "=r"(r[1]), "=r"(r[2]), "=r"(r[3]) : "r"(addr));
}
__device__ __forceinline__ void ldsm_x4_t(uint32_t r[4], uint32_t addr) {
    asm volatile("ldmatrix.sync.aligned.m8n8.x4.trans.shared.b16 {%0,%1,%2,%3}, [%4];"
                 : "=r"(r[0]), "=r"(r[1]), "=r"(r[2]), "=r"(r[3]) : "r"(addr));
}
__device__ __forceinline__ void mma_f16(float c[4], const uint32_t a[4],
                                        uint32_t b0, uint32_t b1) {
    asm volatile(
        "mma.sync.aligned.m16n8k16.row.col.f32.f16.f16.f32 "
        "{%0,%1,%2,%3}, {%4,%5,%6,%7}, {%8,%9}, {%0,%1,%2,%3};"
        : "+f"(c[0]), "+f"(c[1]), "+f"(c[2]), "+f"(c[3])
        : "r"(a[0]), "r"(a[1]), "r"(a[2]), "r"(a[3]), "r"(b0), "r"(b1));
}

// ---------------- fp32 -> fp16 conversion ------------------------------------
__global__ __launch_bounds__(256) void f2h_kernel(const float* __restrict__ src,
                                                  __half* __restrict__ dst)
{
    size_t i = (size_t)blockIdx.x * 256 + threadIdx.x;   // float4 index
    float4 v = reinterpret_cast<const float4*>(src)[i];
    __half2 h0 = __floats2half2_rn(v.x, v.y);
    __half2 h1 = __floats2half2_rn(v.z, v.w);
    reinterpret_cast<__half2*>(dst)[2 * i]     = h0;
    reinterpret_cast<__half2*>(dst)[2 * i + 1] = h1;
}

// ---------------- gating (+ fused feature fp16 conversion) -------------------
__global__ __launch_bounds__(256) void gating_kernel(
    const float* __restrict__ features,
    const float* __restrict__ Wg,
    const float* __restrict__ bg,
    const float* __restrict__ ebias,
    __half* __restrict__ featr)
{
    int warp = threadIdx.x >> 5;
    int lane = threadIdx.x & 31;
    int b = blockIdx.x * 8 + warp;
    if (b >= B_) return;

    const float4* f4 = reinterpret_cast<const float4*>(features + (size_t)b * F_);
    __half2* h2 = reinterpret_cast<__half2*>(featr + (size_t)b * F_);
    float acc[E_];
#pragma unroll
    for (int e = 0; e < E_; e++) acc[e] = 0.f;

    for (int k4 = lane; k4 < F_ / 4; k4 += 32) {
        float4 fv = f4[k4];
        h2[2 * k4]     = __floats2half2_rn(fv.x, fv.y);
        h2[2 * k4 + 1] = __floats2half2_rn(fv.z, fv.w);
#pragma unroll
        for (int e = 0; e < E_; e++) {
            float4 wv = reinterpret_cast<const float4*>(Wg + (size_t)e * F_)[k4];
            acc[e] += fv.x * wv.x + fv.y * wv.y + fv.z * wv.z + fv.w * wv.w;
        }
    }
#pragma unroll
    for (int e = 0; e < E_; e++) {
#pragma unroll
        for (int off = 16; off > 0; off >>= 1)
            acc[e] += __shfl_xor_sync(0xFFFFFFFFu, acc[e], off);
    }
    if (lane == 0) {
        float s[E_];
#pragma unroll
        for (int e = 0; e < E_; e++) s[e] = acc[e] + bg[e] + ebias[e];
        int e0 = 0; float s0 = s[0];
#pragma unroll
        for (int e = 1; e < E_; e++) if (s[e] > s0) { s0 = s[e]; e0 = e; }
        int e1 = -1; float s1 = -3.402823e38f;
#pragma unroll
        for (int e = 0; e < E_; e++) if (e != e0 && s[e] > s1) { s1 = s[e]; e1 = e; }
        float z = expf(s1 - s0);
        float w0 = 1.f / (1.f + z);
        float w1 = z / (1.f + z);
        g_route_e[b] = make_int2(e0, e1);
        g_route_w[b] = make_float2(w0, w1);
    }
}

// ---------------- parallel capacity scan: one block per expert ---------------
__global__ __launch_bounds__(1024) void scan_kernel()
{
    const int e = blockIdx.x;
    const int tid = threadIdx.x;
    const int lane = tid & 31;
    const int wid = tid >> 5;
    __shared__ int warp_cnt[32];

    int base = 0;
    for (int start = 0; start < B_; start += 1024) {
        int b = start + tid;
        int2 re = g_route_e[b];
        bool asg = (re.x == e) || (re.y == e);
        unsigned mask = __ballot_sync(0xFFFFFFFFu, asg);
        int lane_pos = __popc(mask & ((1u << lane) - 1u));
        if (lane == 0) warp_cnt[wid] = __popc(mask);
        __syncthreads();
        int wbase = 0, tot = 0;
#pragma unroll
        for (int j = 0; j < 32; j++) {
            int c = warp_cnt[j];
            if (j < wid) wbase += c;
            tot += c;
        }
        int pos = base + wbase + lane_pos;
        if (asg && pos < CAP_) {
            float2 rw = g_route_w[b];
            g_inv[e * CAP_ + pos] = b;
            g_wslot[e * CAP_ + pos] = (re.x == e) ? rw.x : rw.y;
        }
        base += tot;
        __syncthreads();
    }
    if (tid == 0) g_count[e] = base < CAP_ ? base : CAP_;
}

// ---------------- fp16 tensor-core grouped GEMM ------------------------------
// CTA tile 256(m) x 128(n), BK=64, 4-stage cp.async pipeline, 512 threads.
// 16 warps: wm = wid&7 (8 m-warps of 32 rows), wn = wid>>3 (2 n-warps of 64).
// ONE __syncthreads per k-iteration; 4 k16 sub-steps per iteration give ptxas
// a long barrier-free window to overlap LDSM with MMA.
#define APITCH 144                                  // 128B data + 16B pad
#define BPITCH 272                                  // 256B data + 16B pad
#define STAGE_BYTES (256 * APITCH + 64 * BPITCH)    // 36864 + 17408 = 54272
#define NSTAGE 4
#define SMEM_TOTAL (NSTAGE * STAGE_BYTES)           // 217088

template<int KD, int ND, bool G1>
__global__ __launch_bounds__(512, 1) void moe_gemm(
    const float* __restrict__ bias, float* __restrict__ out)
{
    const int e = blockIdx.z;
    const int cnt = g_count[e];
    const int m0 = blockIdx.x * 256;
    if (m0 >= cnt) return;
    const int n0 = blockIdx.y * 128;
    constexpr int NK = KD / 64;

    extern __shared__ char smem_raw[];
    const uint32_t sbase = smem_u32(smem_raw);

    const int tid  = threadIdx.x;
    const int lane = tid & 31;
    const int wid  = tid >> 5;
    const int wm   = wid & 7;
    const int wn   = wid >> 3;

    // ---- loader setup ----
    // A tasks: 256 rows x 8 chunks (16B) = 2048 -> 4 per thread
    // B tasks: 64 rows x 16 chunks = 1024 -> 2 per thread
    const __half* pA[4];
    uint32_t dA[4];
#pragma unroll
    for (int i = 0; i < 4; i++) {
        int t = tid + 512 * i;
        int arow = t >> 3, achunk = t & 7;
        if (G1) {
            int m = m0 + arow;
            int r = (m < cnt) ? g_inv[e * CAP_ + m] : 0;
            pA[i] = g_featr + (size_t)r * KD + achunk * 8;
        } else {
            pA[i] = g_h + ((size_t)e * CAP_ + m0 + arow) * KD + achunk * 8;
        }
        dA[i] = arow * APITCH + achunk * 16;
    }
    const __half* W = G1 ? g_W1h : g_W2h;
    const __half* pB[2];
    uint32_t dB[2];
#pragma unroll
    for (int i = 0; i < 2; i++) {
        int t = tid + 512 * i;
        int brow = t >> 4, bchunk = t & 15;
        pB[i] = W + (size_t)e * KD * ND + (size_t)brow * ND + n0 + bchunk * 8;
        dB[i] = 256 * APITCH + brow * BPITCH + bchunk * 16;
    }

    auto load_stage = [&](int ko, int s) {
        uint32_t st = sbase + s * STAGE_BYTES;
#pragma unroll
        for (int i = 0; i < 4; i++)
            cp_async16(st + dA[i], pA[i] + (size_t)ko * 64);
#pragma unroll
        for (int i = 0; i < 2; i++)
            cp_async16(st + dB[i], pB[i] + (size_t)ko * 64 * ND);
        cp_commit();
    };

    load_stage(0, 0); load_stage(1, 1); load_stage(2, 2);

    // ---- ldmatrix lane components ----
    const int a_lmrow = wm * 32 + (lane & 7) + ((lane >> 3) & 1) * 8;
    const int a_kb    = (lane >> 4);
    const int b_k     = (lane & 7) + ((lane >> 3) & 1) * 8;
    const int b_nb    = (lane >> 4) * 8;

    float acc[2][8][4];
#pragma unroll
    for (int im = 0; im < 2; im++)
#pragma unroll
        for (int jn = 0; jn < 8; jn++)
#pragma unroll
            for (int q = 0; q < 4; q++) acc[im][jn][q] = 0.f;

    int s_cur = 0;          // i % 4
    int s_load = 3;         // (i+3) % 4
    for (int i = 0; i < NK; i++) {
        if (i <= NK - 3)      cp_wait<2>();
        else if (i == NK - 2) cp_wait<1>();
        else                  cp_wait<0>();
        __syncthreads();
        // refill target (i+3)%4 == (i-1)%4: consumed last iter; barrier above
        // guarantees all warps are past it.
        if (i + 3 < NK) load_stage(i + 3, s_load);

        const uint32_t st = sbase + s_cur * STAGE_BYTES;
#pragma unroll
        for (int kk = 0; kk < 4; kk++) {
            uint32_t a[2][4], b[4][4];
#pragma unroll
            for (int im = 0; im < 2; im++)
                ldsm_x4(a[im], st + (a_lmrow + im * 16) * APITCH + (kk * 2 + a_kb) * 16);
#pragma unroll
            for (int j = 0; j < 4; j++)
                ldsm_x4_t(b[j], st + 256 * APITCH + (kk * 16 + b_k) * BPITCH
                                  + (wn * 64 + j * 16 + b_nb) * 2);
#pragma unroll
            for (int im = 0; im < 2; im++)
#pragma unroll
                for (int jn = 0; jn < 8; jn++)
                    mma_f16(acc[im][jn], a[im], b[jn >> 1][(jn & 1) * 2],
                            b[jn >> 1][(jn & 1) * 2 + 1]);
        }
        if (++s_cur == NSTAGE) s_cur = 0;
        if (++s_load == NSTAGE) s_load = 0;
    }

    // ---- epilogue ----
    const int gID = lane >> 2;
    const int tig = lane & 3;
#pragma unroll
    for (int im = 0; im < 2; im++) {
        int r0 = m0 + wm * 32 + im * 16 + gID;
        int r1 = r0 + 8;
        bool v0 = r0 < cnt, v1 = r1 < cnt;
        if (G1) {
            __half* h0 = g_h + ((size_t)e * CAP_ + r0) * ND;
            __half* h1 = g_h + ((size_t)e * CAP_ + r1) * ND;
#pragma unroll
            for (int jn = 0; jn < 8; jn++) {
                int c = n0 + wn * 64 + jn * 8 + tig * 2;
                float bx = bias[c], by = bias[c + 1];
                if (v0) {
                    __half2 h = __floats2half2_rn(fmaxf(acc[im][jn][0] + bx, 0.f),
                                                  fmaxf(acc[im][jn][1] + by, 0.f));
                    *reinterpret_cast<__half2*>(h0 + c) = h;
                }
                if (v1) {
                    __half2 h = __floats2half2_rn(fmaxf(acc[im][jn][2] + bx, 0.f),
                                                  fmaxf(acc[im][jn][3] + by, 0.f));
                    *reinterpret_cast<__half2*>(h1 + c) = h;
                }
            }
        } else {
            int   i0 = v0 ? g_inv[e * CAP_ + r0] : 0;
            int   i1 = v1 ? g_inv[e * CAP_ + r1] : 0;
            float w0 = v0 ? g_wslot[e * CAP_ + r0] : 0.f;
            float w1 = v1 ? g_wslot[e * CAP_ + r1] : 0.f;
#pragma unroll
            for (int jn = 0; jn < 8; jn++) {
                int c = n0 + wn * 64 + jn * 8 + tig * 2;
                float bx = bias[c], by = bias[c + 1];
                if (v0) {
                    atomicAdd(out + (size_t)i0 * ND + c,     w0 * (acc[im][jn][0] + bx));
                    atomicAdd(out + (size_t)i0 * ND + c + 1, w0 * (acc[im][jn][1] + by));
                }
                if (v1) {
                    atomicAdd(out + (size_t)i1 * ND + c,     w1 * (acc[im][jn][2] + bx));
                    atomicAdd(out + (size_t)i1 * ND + c + 1, w1 * (acc[im][jn][3] + by));
                }
            }
        }
    }
}

// ---------------- launch ------------------------------------------------------
extern "C" void kernel_launch(void* const* d_in, const int* in_sizes, int n_in,
                              void* d_out, int out_size)
{
    const float* features = (const float*)d_in[0];
    const float* Wg       = (const float*)d_in[1];
    const float* bg       = (const float*)d_in[2];
    const float* W1       = (const float*)d_in[3];
    const float* b1       = (const float*)d_in[4];
    const float* W2       = (const float*)d_in[5];
    const float* b2       = (const float*)d_in[6];
    const float* ebias    = (const float*)d_in[7];
    float* out = (float*)d_out;

    cudaFuncSetAttribute(moe_gemm<F_, H_, true>,
                         cudaFuncAttributeMaxDynamicSharedMemorySize, SMEM_TOTAL);
    cudaFuncSetAttribute(moe_gemm<H_, O_, false>,
                         cudaFuncAttributeMaxDynamicSharedMemorySize, SMEM_TOTAL);

    cudaMemsetAsync(out, 0, (size_t)B_ * O_ * sizeof(float), 0);

    __half* d_featr; cudaGetSymbolAddress((void**)&d_featr, g_featr);
    __half* d_W1h;   cudaGetSymbolAddress((void**)&d_W1h, g_W1h);
    __half* d_W2h;   cudaGetSymbolAddress((void**)&d_W2h, g_W2h);

    f2h_kernel<<<((size_t)E_ * F_ * H_ / 4) / 256, 256>>>(W1, d_W1h);
    f2h_kernel<<<((size_t)E_ * H_ * O_ / 4) / 256, 256>>>(W2, d_W2h);
    gating_kernel<<<B_ / 8, 256>>>(features, Wg, bg, ebias, d_featr);
    scan_kernel<<<E_, 1024>>>();

    moe_gemm<F_, H_, true ><<<dim3(CAP_ / 256, H_ / 128, E_), 512, SMEM_TOTAL>>>(b1, nullptr);
    moe_gemm<H_, O_, false><<<dim3(CAP_ / 256, O_ / 128, E_), 512, SMEM_TOTAL>>>(b2, out);
}

// round 8
// speedup vs baseline: 2.2169x; 1.0020x over previous
#include <cuda_runtime.h>
#include <cuda_fp16.h>
#include <math.h>
#include <stdint.h>

// Problem constants
#define B_   16384
#define F_   1024
#define H_   4096
#define O_   1024
#define E_   16
#define CAP_ 2560   // ceil(1.25 * B * 2 / 16)

// ---------------- scratch (device globals; no allocation allowed) ----------
__device__ __half  g_h[(size_t)E_ * CAP_ * H_];     // expert hidden activations (fp16)
__device__ __half  g_featr[(size_t)B_ * F_];        // features in fp16
__device__ __half  g_W1h[(size_t)E_ * F_ * H_];     // W1 in fp16
__device__ __half  g_W2h[(size_t)E_ * H_ * O_];     // W2 in fp16
__device__ int     g_inv[E_ * CAP_];
__device__ float   g_wslot[E_ * CAP_];
__device__ int     g_count[E_];
__device__ int2    g_route_e[B_];
__device__ float2  g_route_w[B_];

// ---------------- helpers ---------------------------------------------------
__device__ __forceinline__ uint32_t smem_u32(const void* p) {
    uint32_t a;
    asm("{ .reg .u64 t; cvta.to.shared.u64 t, %1; cvt.u32.u64 %0, t; }" : "=r"(a) : "l"(p));
    return a;
}
__device__ __forceinline__ void cp_async16(uint32_t dst, const void* src) {
    asm volatile("cp.async.cg.shared.global [%0], [%1], 16;" :: "r"(dst), "l"(src));
}
__device__ __forceinline__ void cp_commit() { asm volatile("cp.async.commit_group;" ::: "memory"); }
template<int N> __device__ __forceinline__ void cp_wait() {
    asm volatile("cp.async.wait_group %0;" :: "n"(N) : "memory");
}
__device__ __forceinline__ void ldsm_x4(uint32_t r[4], uint32_t addr) {
    asm volatile("ldmatrix.sync.aligned.m8n8.x4.shared.b16 {%0,%1,%2,%3}, [%4];"
                 : "=r"(r[0]), "=r"(r[1]), "=r"(r[2]), "=r"(r[3]) : "r"(addr));
}
__device__ __forceinline__ void ldsm_x4_t(uint32_t r[4], uint32_t addr) {
    asm volatile("ldmatrix.sync.aligned.m8n8.x4.trans.shared.b16 {%0,%1,%2,%3}, [%4];"
                 : "=r"(r[0]), "=r"(r[1]), "=r"(r[2]), "=r"(r[3]) : "r"(addr));
}
__device__ __forceinline__ void mma_f16(float c[4], const uint32_t a[4],
                                        uint32_t b0, uint32_t b1) {
    asm volatile(
        "mma.sync.aligned.m16n8k16.row.col.f32.f16.f16.f32 "
        "{%0,%1,%2,%3}, {%4,%5,%6,%7}, {%8,%9}, {%0,%1,%2,%3};"
        : "+f"(c[0]), "+f"(c[1]), "+f"(c[2]), "+f"(c[3])
        : "r"(a[0]), "r"(a[1]), "r"(a[2]), "r"(a[3]), "r"(b0), "r"(b1));
}
__device__ __forceinline__ void red_add_v2(float* addr, float a, float b) {
    asm volatile("red.global.add.v2.f32 [%0], {%1, %2};"
                 :: "l"(addr), "f"(a), "f"(b) : "memory");
}

// ---------------- fused prep: gating (+feat f2h) and weight f2h --------------
#define GATE_BLOCKS (B_ / 8)                 // 2048
#define CONV_BLOCKS 16384
#define CONV_ITERS  8                        // 16384*256*8 = 33.5M float4 = W1+W2

__global__ __launch_bounds__(256) void prep_kernel(
    const float* __restrict__ features,
    const float* __restrict__ Wg,
    const float* __restrict__ bg,
    const float* __restrict__ ebias,
    const float* __restrict__ W1,
    const float* __restrict__ W2,
    __half* __restrict__ featr,
    __half* __restrict__ W1h,
    __half* __restrict__ W2h)
{
    if (blockIdx.x < GATE_BLOCKS) {
        // ---- gating + feature fp16 conversion ----
        int warp = threadIdx.x >> 5;
        int lane = threadIdx.x & 31;
        int b = blockIdx.x * 8 + warp;

        const float4* f4 = reinterpret_cast<const float4*>(features + (size_t)b * F_);
        __half2* h2 = reinterpret_cast<__half2*>(featr + (size_t)b * F_);
        float acc[E_];
#pragma unroll
        for (int e = 0; e < E_; e++) acc[e] = 0.f;

        for (int k4 = lane; k4 < F_ / 4; k4 += 32) {
            float4 fv = f4[k4];
            h2[2 * k4]     = __floats2half2_rn(fv.x, fv.y);
            h2[2 * k4 + 1] = __floats2half2_rn(fv.z, fv.w);
#pragma unroll
            for (int e = 0; e < E_; e++) {
                float4 wv = reinterpret_cast<const float4*>(Wg + (size_t)e * F_)[k4];
                acc[e] += fv.x * wv.x + fv.y * wv.y + fv.z * wv.z + fv.w * wv.w;
            }
        }
#pragma unroll
        for (int e = 0; e < E_; e++) {
#pragma unroll
            for (int off = 16; off > 0; off >>= 1)
                acc[e] += __shfl_xor_sync(0xFFFFFFFFu, acc[e], off);
        }
        if (lane == 0) {
            float s[E_];
#pragma unroll
            for (int e = 0; e < E_; e++) s[e] = acc[e] + bg[e] + ebias[e];
            int e0 = 0; float s0 = s[0];
#pragma unroll
            for (int e = 1; e < E_; e++) if (s[e] > s0) { s0 = s[e]; e0 = e; }
            int e1 = -1; float s1 = -3.402823e38f;
#pragma unroll
            for (int e = 0; e < E_; e++) if (e != e0 && s[e] > s1) { s1 = s[e]; e1 = e; }
            float z = expf(s1 - s0);
            float w0 = 1.f / (1.f + z);
            float w1 = z / (1.f + z);
            g_route_e[b] = make_int2(e0, e1);
            g_route_w[b] = make_float2(w0, w1);
        }
    } else {
        // ---- weight fp32 -> fp16 conversion, grid-stride ----
        constexpr size_t W1_4 = (size_t)E_ * F_ * H_ / 4;   // float4 count
        size_t base = ((size_t)(blockIdx.x - GATE_BLOCKS) * 256 + threadIdx.x);
#pragma unroll
        for (int it = 0; it < CONV_ITERS; it++) {
            size_t i = base + (size_t)it * (CONV_BLOCKS * 256);
            const float* src; __half* dst; size_t j;
            if (i < W1_4) { src = W1; dst = W1h; j = i; }
            else          { src = W2; dst = W2h; j = i - W1_4; }
            float4 v = reinterpret_cast<const float4*>(src)[j];
            reinterpret_cast<__half2*>(dst)[2 * j]     = __floats2half2_rn(v.x, v.y);
            reinterpret_cast<__half2*>(dst)[2 * j + 1] = __floats2half2_rn(v.z, v.w);
        }
    }
}

// ---------------- parallel capacity scan: one block per expert ---------------
__global__ __launch_bounds__(1024) void scan_kernel()
{
    const int e = blockIdx.x;
    const int tid = threadIdx.x;
    const int lane = tid & 31;
    const int wid = tid >> 5;
    __shared__ int warp_cnt[32];

    int base = 0;
    for (int start = 0; start < B_; start += 1024) {
        int b = start + tid;
        int2 re = g_route_e[b];
        bool asg = (re.x == e) || (re.y == e);
        unsigned mask = __ballot_sync(0xFFFFFFFFu, asg);
        int lane_pos = __popc(mask & ((1u << lane) - 1u));
        if (lane == 0) warp_cnt[wid] = __popc(mask);
        __syncthreads();
        int wbase = 0, tot = 0;
#pragma unroll
        for (int j = 0; j < 32; j++) {
            int c = warp_cnt[j];
            if (j < wid) wbase += c;
            tot += c;
        }
        int pos = base + wbase + lane_pos;
        if (asg && pos < CAP_) {
            float2 rw = g_route_w[b];
            g_inv[e * CAP_ + pos] = b;
            g_wslot[e * CAP_ + pos] = (re.x == e) ? rw.x : rw.y;
        }
        base += tot;
        __syncthreads();
    }
    if (tid == 0) g_count[e] = base < CAP_ ? base : CAP_;
}

// ---------------- fp16 tensor-core grouped GEMM ------------------------------
// CTA tile 256(m) x 128(n), BK=64, 4-stage cp.async pipeline, 512 threads.
#define APITCH 144                                  // 128B data + 16B pad
#define BPITCH 272                                  // 256B data + 16B pad
#define STAGE_BYTES (256 * APITCH + 64 * BPITCH)    // 54272
#define NSTAGE 4
#define SMEM_TOTAL (NSTAGE * STAGE_BYTES)           // 217088

template<int KD, int ND, bool G1>
__global__ __launch_bounds__(512, 1) void moe_gemm(
    const float* __restrict__ bias, float* __restrict__ out)
{
    const int e = blockIdx.z;
    const int cnt = g_count[e];
    const int m0 = blockIdx.x * 256;
    if (m0 >= cnt) return;
    const int n0 = blockIdx.y * 128;
    constexpr int NK = KD / 64;

    extern __shared__ char smem_raw[];
    const uint32_t sbase = smem_u32(smem_raw);

    const int tid  = threadIdx.x;
    const int lane = tid & 31;
    const int wid  = tid >> 5;
    const int wm   = wid & 7;
    const int wn   = wid >> 3;

    // ---- loader setup ----
    const __half* pA[4];
    uint32_t dA[4];
#pragma unroll
    for (int i = 0; i < 4; i++) {
        int t = tid + 512 * i;
        int arow = t >> 3, achunk = t & 7;
        if (G1) {
            int m = m0 + arow;
            int r = (m < cnt) ? g_inv[e * CAP_ + m] : 0;
            pA[i] = g_featr + (size_t)r * KD + achunk * 8;
        } else {
            pA[i] = g_h + ((size_t)e * CAP_ + m0 + arow) * KD + achunk * 8;
        }
        dA[i] = arow * APITCH + achunk * 16;
    }
    const __half* W = G1 ? g_W1h : g_W2h;
    const __half* pB[2];
    uint32_t dB[2];
#pragma unroll
    for (int i = 0; i < 2; i++) {
        int t = tid + 512 * i;
        int brow = t >> 4, bchunk = t & 15;
        pB[i] = W + (size_t)e * KD * ND + (size_t)brow * ND + n0 + bchunk * 8;
        dB[i] = 256 * APITCH + brow * BPITCH + bchunk * 16;
    }

    auto load_stage = [&](int ko, int s) {
        uint32_t st = sbase + s * STAGE_BYTES;
#pragma unroll
        for (int i = 0; i < 4; i++)
            cp_async16(st + dA[i], pA[i] + (size_t)ko * 64);
#pragma unroll
        for (int i = 0; i < 2; i++)
            cp_async16(st + dB[i], pB[i] + (size_t)ko * 64 * ND);
        cp_commit();
    };

    load_stage(0, 0); load_stage(1, 1); load_stage(2, 2);

    // ---- ldmatrix lane components ----
    const int a_lmrow = wm * 32 + (lane & 7) + ((lane >> 3) & 1) * 8;
    const int a_kb    = (lane >> 4);
    const int b_k     = (lane & 7) + ((lane >> 3) & 1) * 8;
    const int b_nb    = (lane >> 4) * 8;

    float acc[2][8][4];
#pragma unroll
    for (int im = 0; im < 2; im++)
#pragma unroll
        for (int jn = 0; jn < 8; jn++)
#pragma unroll
            for (int q = 0; q < 4; q++) acc[im][jn][q] = 0.f;

    int s_cur = 0;          // i % 4
    int s_load = 3;         // (i+3) % 4
    for (int i = 0; i < NK; i++) {
        if (i <= NK - 3)      cp_wait<2>();
        else if (i == NK - 2) cp_wait<1>();
        else                  cp_wait<0>();
        __syncthreads();
        // refill target (i+3)%4 == (i-1)%4: consumed last iter; barrier above
        // guarantees all warps are past it.
        if (i + 3 < NK) load_stage(i + 3, s_load);

        const uint32_t st = sbase + s_cur * STAGE_BYTES;
#pragma unroll
        for (int kk = 0; kk < 4; kk++) {
            uint32_t a[2][4], b[4][4];
#pragma unroll
            for (int im = 0; im < 2; im++)
                ldsm_x4(a[im], st + (a_lmrow + im * 16) * APITCH + (kk * 2 + a_kb) * 16);
#pragma unroll
            for (int j = 0; j < 4; j++)
                ldsm_x4_t(b[j], st + 256 * APITCH + (kk * 16 + b_k) * BPITCH
                                  + (wn * 64 + j * 16 + b_nb) * 2);
#pragma unroll
            for (int im = 0; im < 2; im++)
#pragma unroll
                for (int jn = 0; jn < 8; jn++)
                    mma_f16(acc[im][jn], a[im], b[jn >> 1][(jn & 1) * 2],
                            b[jn >> 1][(jn & 1) * 2 + 1]);
        }
        if (++s_cur == NSTAGE) s_cur = 0;
        if (++s_load == NSTAGE) s_load = 0;
    }

    // ---- epilogue ----
    const int gID = lane >> 2;
    const int tig = lane & 3;
#pragma unroll
    for (int im = 0; im < 2; im++) {
        int r0 = m0 + wm * 32 + im * 16 + gID;
        int r1 = r0 + 8;
        bool v0 = r0 < cnt, v1 = r1 < cnt;
        if (G1) {
            __half* h0 = g_h + ((size_t)e * CAP_ + r0) * ND;
            __half* h1 = g_h + ((size_t)e * CAP_ + r1) * ND;
#pragma unroll
            for (int jn = 0; jn < 8; jn++) {
                int c = n0 + wn * 64 + jn * 8 + tig * 2;
                float bx = bias[c], by = bias[c + 1];
                if (v0) {
                    __half2 h = __floats2half2_rn(fmaxf(acc[im][jn][0] + bx, 0.f),
                                                  fmaxf(acc[im][jn][1] + by, 0.f));
                    *reinterpret_cast<__half2*>(h0 + c) = h;
                }
                if (v1) {
                    __half2 h = __floats2half2_rn(fmaxf(acc[im][jn][2] + bx, 0.f),
                                                  fmaxf(acc[im][jn][3] + by, 0.f));
                    *reinterpret_cast<__half2*>(h1 + c) = h;
                }
            }
        } else {
            int   i0 = v0 ? g_inv[e * CAP_ + r0] : 0;
            int   i1 = v1 ? g_inv[e * CAP_ + r1] : 0;
            float w0 = v0 ? g_wslot[e * CAP_ + r0] : 0.f;
            float w1 = v1 ? g_wslot[e * CAP_ + r1] : 0.f;
#pragma unroll
            for (int jn = 0; jn < 8; jn++) {
                int c = n0 + wn * 64 + jn * 8 + tig * 2;
                float bx = bias[c], by = bias[c + 1];
                if (v0) {
                    red_add_v2(out + (size_t)i0 * ND + c,
                               w0 * (acc[im][jn][0] + bx),
                               w0 * (acc[im][jn][1] + by));
                }
                if (v1) {
                    red_add_v2(out + (size_t)i1 * ND + c,
                               w1 * (acc[im][jn][2] + bx),
                               w1 * (acc[im][jn][3] + by));
                }
            }
        }
    }
}

// ---------------- launch ------------------------------------------------------
extern "C" void kernel_launch(void* const* d_in, const int* in_sizes, int n_in,
                              void* d_out, int out_size)
{
    const float* features = (const float*)d_in[0];
    const float* Wg       = (const float*)d_in[1];
    const float* bg       = (const float*)d_in[2];
    const float* W1       = (const float*)d_in[3];
    const float* b1       = (const float*)d_in[4];
    const float* W2       = (const float*)d_in[5];
    const float* b2       = (const float*)d_in[6];
    const float* ebias    = (const float*)d_in[7];
    float* out = (float*)d_out;

    cudaFuncSetAttribute(moe_gemm<F_, H_, true>,
                         cudaFuncAttributeMaxDynamicSharedMemorySize, SMEM_TOTAL);
    cudaFuncSetAttribute(moe_gemm<H_, O_, false>,
                         cudaFuncAttributeMaxDynamicSharedMemorySize, SMEM_TOTAL);

    cudaMemsetAsync(out, 0, (size_t)B_ * O_ * sizeof(float), 0);

    __half* d_featr; cudaGetSymbolAddress((void**)&d_featr, g_featr);
    __half* d_W1h;   cudaGetSymbolAddress((void**)&d_W1h, g_W1h);
    __half* d_W2h;   cudaGetSymbolAddress((void**)&d_W2h, g_W2h);

    prep_kernel<<<GATE_BLOCKS + CONV_BLOCKS, 256>>>(
        features, Wg, bg, ebias, W1, W2, d_featr, d_W1h, d_W2h);
    scan_kernel<<<E_, 1024>>>();

    moe_gemm<F_, H_, true ><<<dim3(CAP_ / 256, H_ / 128, E_), 512, SMEM_TOTAL>>>(b1, nullptr);
    moe_gemm<H_, O_, false><<<dim3(CAP_ / 256, O_ / 128, E_), 512, SMEM_TOTAL>>>(b2, out);
}

// round 9
// speedup vs baseline: 2.2193x; 1.0010x over previous
#include <cuda_runtime.h>
#include <cuda_fp16.h>
#include <math.h>
#include <stdint.h>

// Problem constants
#define B_   16384
#define F_   1024
#define H_   4096
#define O_   1024
#define E_   16
#define CAP_ 2560   // ceil(1.25 * B * 2 / 16)

// ---------------- scratch (device globals; no allocation allowed) ----------
__device__ __half  g_h[(size_t)E_ * CAP_ * H_];     // expert hidden activations (fp16)
__device__ __half  g_featr[(size_t)B_ * F_];        // features in fp16
__device__ __half  g_W1h[(size_t)E_ * F_ * H_];     // W1 in fp16
__device__ __half  g_W2h[(size_t)E_ * H_ * O_];     // W2 in fp16
__device__ int     g_inv[E_ * CAP_];
__device__ float   g_wslot[E_ * CAP_];
__device__ int     g_count[E_];
__device__ int2    g_route_e[B_];
__device__ float2  g_route_w[B_];

// ---------------- helpers ---------------------------------------------------
__device__ __forceinline__ uint32_t smem_u32(const void* p) {
    uint32_t a;
    asm("{ .reg .u64 t; cvta.to.shared.u64 t, %1; cvt.u32.u64 %0, t; }" : "=r"(a) : "l"(p));
    return a;
}
__device__ __forceinline__ void cp_async16(uint32_t dst, const void* src) {
    asm volatile("cp.async.cg.shared.global [%0], [%1], 16;" :: "r"(dst), "l"(src));
}
__device__ __forceinline__ void cp_commit() { asm volatile("cp.async.commit_group;" ::: "memory"); }
template<int N> __device__ __forceinline__ void cp_wait() {
    asm volatile("cp.async.wait_group %0;" :: "n"(N) : "memory");
}
__device__ __forceinline__ void ldsm_x4(uint32_t r[4], uint32_t addr) {
    asm volatile("ldmatrix.sync.aligned.m8n8.x4.shared.b16 {%0,%1,%2,%3}, [%4];"
                 : "=r"(r[0]), "=r"(r[1]), "=r"(r[2]), "=r"(r[3]) : "r"(addr));
}
__device__ __forceinline__ void ldsm_x4_t(uint32_t r[4], uint32_t addr) {
    asm volatile("ldmatrix.sync.aligned.m8n8.x4.trans.shared.b16 {%0,%1,%2,%3}, [%4];"
                 : "=r"(r[0]), "=r"(r[1]), "=r"(r[2]), "=r"(r[3]) : "r"(addr));
}
__device__ __forceinline__ void mma_f16(float c[4], const uint32_t a[4],
                                        uint32_t b0, uint32_t b1) {
    asm volatile(
        "mma.sync.aligned.m16n8k16.row.col.f32.f16.f16.f32 "
        "{%0,%1,%2,%3}, {%4,%5,%6,%7}, {%8,%9}, {%0,%1,%2,%3};"
        : "+f"(c[0]), "+f"(c[1]), "+f"(c[2]), "+f"(c[3])
        : "r"(a[0]), "r"(a[1]), "r"(a[2]), "r"(a[3]), "r"(b0), "r"(b1));
}
__device__ __forceinline__ void red_add_v2(float* addr, float a, float b) {
    asm volatile("red.global.add.v2.f32 [%0], {%1, %2};"
                 :: "l"(addr), "f"(a), "f"(b) : "memory");
}

// ---------------- fused prep: gating (+feat f2h) and W1 f2h ------------------
#define GATE_BLOCKS (B_ / 8)                 // 2048
#define CONV_BLOCKS 8192
#define CONV_ITERS  8                        // 8192*256*8 = 16.78M float4 = W1

__global__ __launch_bounds__(256) void prep_kernel(
    const float* __restrict__ features,
    const float* __restrict__ Wg,
    const float* __restrict__ bg,
    const float* __restrict__ ebias,
    const float* __restrict__ W1,
    __half* __restrict__ featr,
    __half* __restrict__ W1h)
{
    if (blockIdx.x < GATE_BLOCKS) {
        int warp = threadIdx.x >> 5;
        int lane = threadIdx.x & 31;
        int b = blockIdx.x * 8 + warp;

        const float4* f4 = reinterpret_cast<const float4*>(features + (size_t)b * F_);
        __half2* h2 = reinterpret_cast<__half2*>(featr + (size_t)b * F_);
        float acc[E_];
#pragma unroll
        for (int e = 0; e < E_; e++) acc[e] = 0.f;

        for (int k4 = lane; k4 < F_ / 4; k4 += 32) {
            float4 fv = f4[k4];
            h2[2 * k4]     = __floats2half2_rn(fv.x, fv.y);
            h2[2 * k4 + 1] = __floats2half2_rn(fv.z, fv.w);
#pragma unroll
            for (int e = 0; e < E_; e++) {
                float4 wv = reinterpret_cast<const float4*>(Wg + (size_t)e * F_)[k4];
                acc[e] += fv.x * wv.x + fv.y * wv.y + fv.z * wv.z + fv.w * wv.w;
            }
        }
#pragma unroll
        for (int e = 0; e < E_; e++) {
#pragma unroll
            for (int off = 16; off > 0; off >>= 1)
                acc[e] += __shfl_xor_sync(0xFFFFFFFFu, acc[e], off);
        }
        if (lane == 0) {
            float s[E_];
#pragma unroll
            for (int e = 0; e < E_; e++) s[e] = acc[e] + bg[e] + ebias[e];
            int e0 = 0; float s0 = s[0];
#pragma unroll
            for (int e = 1; e < E_; e++) if (s[e] > s0) { s0 = s[e]; e0 = e; }
            int e1 = -1; float s1 = -3.402823e38f;
#pragma unroll
            for (int e = 0; e < E_; e++) if (e != e0 && s[e] > s1) { s1 = s[e]; e1 = e; }
            float z = expf(s1 - s0);
            float w0 = 1.f / (1.f + z);
            float w1 = z / (1.f + z);
            g_route_e[b] = make_int2(e0, e1);
            g_route_w[b] = make_float2(w0, w1);
        }
    } else {
        size_t base = ((size_t)(blockIdx.x - GATE_BLOCKS) * 256 + threadIdx.x);
#pragma unroll
        for (int it = 0; it < CONV_ITERS; it++) {
            size_t j = base + (size_t)it * (CONV_BLOCKS * 256);
            float4 v = reinterpret_cast<const float4*>(W1)[j];
            reinterpret_cast<__half2*>(W1h)[2 * j]     = __floats2half2_rn(v.x, v.y);
            reinterpret_cast<__half2*>(W1h)[2 * j + 1] = __floats2half2_rn(v.z, v.w);
        }
    }
}

// ---------------- parallel capacity scan: one block per expert ---------------
__global__ __launch_bounds__(1024) void scan_kernel()
{
    const int e = blockIdx.x;
    const int tid = threadIdx.x;
    const int lane = tid & 31;
    const int wid = tid >> 5;
    __shared__ int warp_cnt[32];

    int base = 0;
    for (int start = 0; start < B_; start += 1024) {
        int b = start + tid;
        int2 re = g_route_e[b];
        bool asg = (re.x == e) || (re.y == e);
        unsigned mask = __ballot_sync(0xFFFFFFFFu, asg);
        int lane_pos = __popc(mask & ((1u << lane) - 1u));
        if (lane == 0) warp_cnt[wid] = __popc(mask);
        __syncthreads();
        int wbase = 0, tot = 0;
#pragma unroll
        for (int j = 0; j < 32; j++) {
            int c = warp_cnt[j];
            if (j < wid) wbase += c;
            tot += c;
        }
        int pos = base + wbase + lane_pos;
        if (asg && pos < CAP_) {
            float2 rw = g_route_w[b];
            g_inv[e * CAP_ + pos] = b;
            g_wslot[e * CAP_ + pos] = (re.x == e) ? rw.x : rw.y;
        }
        base += tot;
        __syncthreads();
    }
    if (tid == 0) g_count[e] = base < CAP_ ? base : CAP_;
}

// ---------------- fp16 tensor-core grouped GEMM ------------------------------
// CTA tile 256(m) x 128(n), BK=64, 4-stage cp.async pipeline, 512 threads.
// kk order is staggered per warp (wid&3) to desynchronize LDSM bursts (smem
// crossbar) from MMA bursts (tensor pipe) across warp groups.
// For G1, extra blockIdx.x slices (>= MX) convert W2 fp32->fp16 instead
// (completes within this kernel; GEMM2 launched after, so ordering is safe).
#define APITCH 144                                  // 128B data + 16B pad
#define BPITCH 272                                  // 256B data + 16B pad
#define STAGE_BYTES (256 * APITCH + 64 * BPITCH)    // 54272
#define NSTAGE 4
#define SMEM_TOTAL (NSTAGE * STAGE_BYTES)           // 217088
#define MX (CAP_ / 256)                             // 10 gemm x-slices

template<int KD, int ND, bool G1>
__global__ __launch_bounds__(512, 1) void moe_gemm(
    const float* __restrict__ bias, float* __restrict__ out,
    const float* __restrict__ Wsrc, __half* __restrict__ Wdst)
{
    if (G1 && blockIdx.x >= MX) {
        // ---- W2 fp32 -> fp16 conversion slice (1024 CTAs x 16384 float4) ----
        int c = ((blockIdx.z * (int)gridDim.y + blockIdx.y) * 2 + ((int)blockIdx.x - MX));
        size_t base = (size_t)c * 16384 + threadIdx.x;
#pragma unroll
        for (int it = 0; it < 32; it++) {
            size_t j = base + (size_t)it * 512;
            float4 v = reinterpret_cast<const float4*>(Wsrc)[j];
            reinterpret_cast<__half2*>(Wdst)[2 * j]     = __floats2half2_rn(v.x, v.y);
            reinterpret_cast<__half2*>(Wdst)[2 * j + 1] = __floats2half2_rn(v.z, v.w);
        }
        return;
    }

    const int e = blockIdx.z;
    const int cnt = g_count[e];
    const int m0 = blockIdx.x * 256;
    if (m0 >= cnt) return;
    const int n0 = blockIdx.y * 128;
    constexpr int NK = KD / 64;

    extern __shared__ char smem_raw[];
    const uint32_t sbase = smem_u32(smem_raw);

    const int tid  = threadIdx.x;
    const int lane = tid & 31;
    const int wid  = tid >> 5;
    const int wm   = wid & 7;
    const int wn   = wid >> 3;
    const int kst  = wid & 3;      // kk stagger offset

    // ---- loader setup ----
    const __half* pA[4];
    uint32_t dA[4];
#pragma unroll
    for (int i = 0; i < 4; i++) {
        int t = tid + 512 * i;
        int arow = t >> 3, achunk = t & 7;
        if (G1) {
            int m = m0 + arow;
            int r = (m < cnt) ? g_inv[e * CAP_ + m] : 0;
            pA[i] = g_featr + (size_t)r * KD + achunk * 8;
        } else {
            pA[i] = g_h + ((size_t)e * CAP_ + m0 + arow) * KD + achunk * 8;
        }
        dA[i] = arow * APITCH + achunk * 16;
    }
    const __half* W = G1 ? g_W1h : g_W2h;
    const __half* pB[2];
    uint32_t dB[2];
#pragma unroll
    for (int i = 0; i < 2; i++) {
        int t = tid + 512 * i;
        int brow = t >> 4, bchunk = t & 15;
        pB[i] = W + (size_t)e * KD * ND + (size_t)brow * ND + n0 + bchunk * 8;
        dB[i] = 256 * APITCH + brow * BPITCH + bchunk * 16;
    }

    auto load_stage = [&](int ko, int s) {
        uint32_t st = sbase + s * STAGE_BYTES;
#pragma unroll
        for (int i = 0; i < 4; i++)
            cp_async16(st + dA[i], pA[i] + (size_t)ko * 64);
#pragma unroll
        for (int i = 0; i < 2; i++)
            cp_async16(st + dB[i], pB[i] + (size_t)ko * 64 * ND);
        cp_commit();
    };

    load_stage(0, 0); load_stage(1, 1); load_stage(2, 2);

    // ---- ldmatrix lane components ----
    const int a_lmrow = wm * 32 + (lane & 7) + ((lane >> 3) & 1) * 8;
    const int a_kb    = (lane >> 4);
    const int b_k     = (lane & 7) + ((lane >> 3) & 1) * 8;
    const int b_nb    = (lane >> 4) * 8;

    float acc[2][8][4];
#pragma unroll
    for (int im = 0; im < 2; im++)
#pragma unroll
        for (int jn = 0; jn < 8; jn++)
#pragma unroll
            for (int q = 0; q < 4; q++) acc[im][jn][q] = 0.f;

    int s_cur = 0;          // i % 4
    int s_load = 3;         // (i+3) % 4
    for (int i = 0; i < NK; i++) {
        cp_wait<2>();       // uniform: one commit per iter (real or empty)
        __syncthreads();
        if (i + 3 < NK) load_stage(i + 3, s_load);
        else            cp_commit();

        const uint32_t st = sbase + s_cur * STAGE_BYTES;
#pragma unroll
        for (int kq = 0; kq < 4; kq++) {
            const int kk = (kq + kst) & 3;   // staggered k16 order per warp
            uint32_t a[2][4], b[4][4];
#pragma unroll
            for (int im = 0; im < 2; im++)
                ldsm_x4(a[im], st + (a_lmrow + im * 16) * APITCH + (kk * 2 + a_kb) * 16);
#pragma unroll
            for (int j = 0; j < 4; j++)
                ldsm_x4_t(b[j], st + 256 * APITCH + (kk * 16 + b_k) * BPITCH
                                  + (wn * 64 + j * 16 + b_nb) * 2);
#pragma unroll
            for (int im = 0; im < 2; im++)
#pragma unroll
                for (int jn = 0; jn < 8; jn++)
                    mma_f16(acc[im][jn], a[im], b[jn >> 1][(jn & 1) * 2],
                            b[jn >> 1][(jn & 1) * 2 + 1]);
        }
        if (++s_cur == NSTAGE) s_cur = 0;
        if (++s_load == NSTAGE) s_load = 0;
    }

    // ---- epilogue ----
    const int gID = lane >> 2;
    const int tig = lane & 3;
#pragma unroll
    for (int im = 0; im < 2; im++) {
        int r0 = m0 + wm * 32 + im * 16 + gID;
        int r1 = r0 + 8;
        bool v0 = r0 < cnt, v1 = r1 < cnt;
        if (G1) {
            __half* h0 = g_h + ((size_t)e * CAP_ + r0) * ND;
            __half* h1 = g_h + ((size_t)e * CAP_ + r1) * ND;
#pragma unroll
            for (int jn = 0; jn < 8; jn++) {
                int c = n0 + wn * 64 + jn * 8 + tig * 2;
                float bx = bias[c], by = bias[c + 1];
                if (v0) {
                    __half2 h = __floats2half2_rn(fmaxf(acc[im][jn][0] + bx, 0.f),
                                                  fmaxf(acc[im][jn][1] + by, 0.f));
                    *reinterpret_cast<__half2*>(h0 + c) = h;
                }
                if (v1) {
                    __half2 h = __floats2half2_rn(fmaxf(acc[im][jn][2] + bx, 0.f),
                                                  fmaxf(acc[im][jn][3] + by, 0.f));
                    *reinterpret_cast<__half2*>(h1 + c) = h;
                }
            }
        } else {
            int   i0 = v0 ? g_inv[e * CAP_ + r0] : 0;
            int   i1 = v1 ? g_inv[e * CAP_ + r1] : 0;
            float w0 = v0 ? g_wslot[e * CAP_ + r0] : 0.f;
            float w1 = v1 ? g_wslot[e * CAP_ + r1] : 0.f;
#pragma unroll
            for (int jn = 0; jn < 8; jn++) {
                int c = n0 + wn * 64 + jn * 8 + tig * 2;
                float bx = bias[c], by = bias[c + 1];
                if (v0) {
                    red_add_v2(out + (size_t)i0 * ND + c,
                               w0 * (acc[im][jn][0] + bx),
                               w0 * (acc[im][jn][1] + by));
                }
                if (v1) {
                    red_add_v2(out + (size_t)i1 * ND + c,
                               w1 * (acc[im][jn][2] + bx),
                               w1 * (acc[im][jn][3] + by));
                }
            }
        }
    }
}

// ---------------- launch ------------------------------------------------------
extern "C" void kernel_launch(void* const* d_in, const int* in_sizes, int n_in,
                              void* d_out, int out_size)
{
    const float* features = (const float*)d_in[0];
    const float* Wg       = (const float*)d_in[1];
    const float* bg       = (const float*)d_in[2];
    const float* W1       = (const float*)d_in[3];
    const float* b1       = (const float*)d_in[4];
    const float* W2       = (const float*)d_in[5];
    const float* b2       = (const float*)d_in[6];
    const float* ebias    = (const float*)d_in[7];
    float* out = (float*)d_out;

    cudaFuncSetAttribute(moe_gemm<F_, H_, true>,
                         cudaFuncAttributeMaxDynamicSharedMemorySize, SMEM_TOTAL);
    cudaFuncSetAttribute(moe_gemm<H_, O_, false>,
                         cudaFuncAttributeMaxDynamicSharedMemorySize, SMEM_TOTAL);

    cudaMemsetAsync(out, 0, (size_t)B_ * O_ * sizeof(float), 0);

    __half* d_featr; cudaGetSymbolAddress((void**)&d_featr, g_featr);
    __half* d_W1h;   cudaGetSymbolAddress((void**)&d_W1h, g_W1h);
    __half* d_W2h;   cudaGetSymbolAddress((void**)&d_W2h, g_W2h);

    prep_kernel<<<GATE_BLOCKS + CONV_BLOCKS, 256>>>(
        features, Wg, bg, ebias, W1, d_featr, d_W1h);
    scan_kernel<<<E_, 1024>>>();

    // GEMM1 grid carries 2 extra x-slices that convert W2 (done before GEMM2).
    moe_gemm<F_, H_, true ><<<dim3(MX + 2, H_ / 128, E_), 512, SMEM_TOTAL>>>(
        b1, nullptr, W2, d_W2h);
    moe_gemm<H_, O_, false><<<dim3(MX, O_ / 128, E_), 512, SMEM_TOTAL>>>(
        b2, out, nullptr, nullptr);
}